// round 3
// baseline (speedup 1.0000x reference)
#include <cuda_runtime.h>
#include <math.h>

// Problem constants
#define NT   768      // T = N*M flattened nodes
#define HD   64       // hidden dim
#define FD   32       // feature dim
#define KD   2        // equivariant vector channels
#define LL   2        // layers
#define OUTD 64       // invariant out
#define VEC_OUT (NT * KD * 3)          // 4608
#define INV_T1 (1.0f / 767.0f)         // 1/(T-1)

// ---------------- device scratch (no allocs allowed) ----------------
__device__ float g_h[NT * HD];     // node features
__device__ float g_x[NT * 6];      // x_vec [T][K=2][3]
__device__ float g_A[NT * HD];     // h@we1_sender
__device__ float g_B[NT * HD];     // h@we1_receiver + be1
__device__ float g_agg[NT * HD];   // segment sum of m
__device__ float g_xupd[NT * 6];   // segment sum of upd

__device__ __forceinline__ float silu(float x) {
    return x * __fdividef(1.0f, 1.0f + __expf(-x));
}

// ---------------- init: h = feat@w_emb + b_emb ; x = repeat(pos, K) --------
__global__ void k_init(const float* __restrict__ feat,
                       const float* __restrict__ w_emb,
                       const float* __restrict__ b_emb,
                       const float* __restrict__ pos) {
    __shared__ float f[FD];
    int t = blockIdx.x, j = threadIdx.x;
    if (j < FD) f[j] = feat[t * FD + j];
    __syncthreads();
    float acc = b_emb[j];
#pragma unroll
    for (int i = 0; i < FD; i++) acc += f[i] * w_emb[i * HD + j];
    g_h[t * HD + j] = acc;
    if (j < 6) g_x[t * 6 + j] = pos[t * 3 + (j % 3)];
}

// ---------------- per-node precompute for edge layer ----------------
// A[t] = h[t] @ we1[l][0:64], B[t] = h[t] @ we1[l][64:128] + be1[l]
__global__ void k_pre(const float* __restrict__ we1,
                      const float* __restrict__ be1, int layer) {
    const float* w = we1 + layer * 130 * HD;
    __shared__ float hs[HD];
    int t = blockIdx.x, j = threadIdx.x;
    hs[j] = g_h[t * HD + j];
    __syncthreads();
    float a = 0.0f, b = be1[layer * HD + j];
#pragma unroll 8
    for (int i = 0; i < HD; i++) {
        float hv = hs[i];
        a += hv * w[i * HD + j];
        b += hv * w[(64 + i) * HD + j];
    }
    g_A[t * HD + j] = a;
    g_B[t * HD + j] = b;
}

// ---------------- the big edge kernel: one block per receiver ----------------
__global__ __launch_bounds__(256) void k_edge(
    const float* __restrict__ we1, const float* __restrict__ we2,
    const float* __restrict__ be2, const float* __restrict__ wx1,
    const float* __restrict__ bx1, const float* __restrict__ wx2,
    int layer) {
    const float* we1l = we1 + layer * 130 * HD;
    const float* we2l = we2 + layer * HD * HD;
    const float* be2l = be2 + layer * HD;
    const float* wx1l = wx1 + layer * HD * HD;
    const float* bx1l = bx1 + layer * HD;
    const float* wx2l = wx2 + layer * HD * KD;

    __shared__ float2 sW2[HD * 32];   // we2 column pairs: sW2[i][j]=(we2[i][j],we2[i][j+32])
    __shared__ float2 sWX[HD * 32];   // wx1 column pairs
    __shared__ float sAgg[HD];
    __shared__ float sXu[6];

    const int r = blockIdx.x;
    const int tid = threadIdx.x;
    const int warp = tid >> 5, lane = tid & 31;

    for (int idx = tid; idx < HD * 32; idx += 256) {
        int i = idx >> 5, j = idx & 31;
        sW2[idx] = make_float2(we2l[i * HD + j], we2l[i * HD + j + 32]);
        sWX[idx] = make_float2(wx1l[i * HD + j], wx1l[i * HD + j + 32]);
    }
    if (tid < HD) sAgg[tid] = 0.0f;
    if (tid < 6) sXu[tid] = 0.0f;
    __syncthreads();

    // hoisted per-lane constants (lane owns channels lane, lane+32)
    const float Cr0 = g_B[r * HD + lane], Cr1 = g_B[r * HD + lane + 32];
    const float wq00 = we1l[128 * HD + lane], wq01 = we1l[128 * HD + lane + 32];
    const float wq10 = we1l[129 * HD + lane], wq11 = we1l[129 * HD + lane + 32];
    const float bb20 = be2l[lane], bb21 = be2l[lane + 32];
    const float bxl0 = bx1l[lane], bxl1 = bx1l[lane + 32];
    const float wx2_00 = wx2l[lane * 2 + 0], wx2_01 = wx2l[lane * 2 + 1];
    const float wx2_10 = wx2l[(lane + 32) * 2 + 0], wx2_11 = wx2l[(lane + 32) * 2 + 1];
    float xr[6];
#pragma unroll
    for (int c = 0; c < 6; c++) xr[c] = g_x[r * 6 + c];

    float agg0 = 0.0f, agg1 = 0.0f;
    float xacc[6] = {0, 0, 0, 0, 0, 0};

    // each warp handles sender pairs: base, base+1
    for (int base = warp * 2; base < NT; base += 16) {
        float t0[2], t1[2];           // silu'd layer-1 act, channels lane / lane+32
        float d[2][6], sq[2][2], valid[2];
#pragma unroll
        for (int e = 0; e < 2; e++) {
            int s = base + e;
            valid[e] = (s != r) ? 1.0f : 0.0f;
#pragma unroll
            for (int c = 0; c < 6; c++) d[e][c] = g_x[s * 6 + c] - xr[c];
            sq[e][0] = d[e][0] * d[e][0] + d[e][1] * d[e][1] + d[e][2] * d[e][2];
            sq[e][1] = d[e][3] * d[e][3] + d[e][4] * d[e][4] + d[e][5] * d[e][5];
            float a0 = g_A[s * HD + lane];
            float a1 = g_A[s * HD + lane + 32];
            float p0 = a0 + Cr0 + sq[e][0] * wq00 + sq[e][1] * wq10;
            float p1 = a1 + Cr1 + sq[e][0] * wq01 + sq[e][1] * wq11;
            t0[e] = silu(p0);
            t1[e] = silu(p1);
        }

        // m = silu(t @ we2 + be2)
        float m0[2] = {bb20, bb20}, m1[2] = {bb21, bb21};
#pragma unroll
        for (int i = 0; i < 32; i++) {
            float2 w = sW2[i * 32 + lane];
            float a0 = __shfl_sync(0xffffffffu, t0[0], i);
            float a1 = __shfl_sync(0xffffffffu, t0[1], i);
            m0[0] += a0 * w.x; m1[0] += a0 * w.y;
            m0[1] += a1 * w.x; m1[1] += a1 * w.y;
        }
#pragma unroll
        for (int i = 0; i < 32; i++) {
            float2 w = sW2[(i + 32) * 32 + lane];
            float a0 = __shfl_sync(0xffffffffu, t1[0], i);
            float a1 = __shfl_sync(0xffffffffu, t1[1], i);
            m0[0] += a0 * w.x; m1[0] += a0 * w.y;
            m0[1] += a1 * w.x; m1[1] += a1 * w.y;
        }
#pragma unroll
        for (int e = 0; e < 2; e++) {
            m0[e] = silu(m0[e]) * valid[e];   // mask self-edge
            m1[e] = silu(m1[e]) * valid[e];
        }
        agg0 += m0[0] + m0[1];
        agg1 += m1[0] + m1[1];

        // p = silu(m @ wx1 + bx1)
        float p0[2] = {bxl0, bxl0}, p1[2] = {bxl1, bxl1};
#pragma unroll
        for (int i = 0; i < 32; i++) {
            float2 w = sWX[i * 32 + lane];
            float a0 = __shfl_sync(0xffffffffu, m0[0], i);
            float a1 = __shfl_sync(0xffffffffu, m0[1], i);
            p0[0] += a0 * w.x; p1[0] += a0 * w.y;
            p0[1] += a1 * w.x; p1[1] += a1 * w.y;
        }
#pragma unroll
        for (int i = 0; i < 32; i++) {
            float2 w = sWX[(i + 32) * 32 + lane];
            float a0 = __shfl_sync(0xffffffffu, m1[0], i);
            float a1 = __shfl_sync(0xffffffffu, m1[1], i);
            p0[0] += a0 * w.x; p1[0] += a0 * w.y;
            p0[1] += a1 * w.x; p1[1] += a1 * w.y;
        }

#pragma unroll
        for (int e = 0; e < 2; e++) {
            float q0 = silu(p0[e]), q1 = silu(p1[e]);
            // phi[k] = sum_j q[j] * wx2[j][k] ; lane partial then butterfly
            float ph0 = q0 * wx2_00 + q1 * wx2_10;
            float ph1 = q0 * wx2_01 + q1 * wx2_11;
#pragma unroll
            for (int off = 16; off > 0; off >>= 1) {
                ph0 += __shfl_xor_sync(0xffffffffu, ph0, off);
                ph1 += __shfl_xor_sync(0xffffffffu, ph1, off);
            }
            // upd = phi * diff / (sqrt(sq+1e-8)+1); diff==0 on self-edge -> exact 0
            float s0 = ph0 * __fdividef(1.0f, sqrtf(sq[e][0] + 1e-8f) + 1.0f);
            float s1 = ph1 * __fdividef(1.0f, sqrtf(sq[e][1] + 1e-8f) + 1.0f);
            xacc[0] += s0 * d[e][0];
            xacc[1] += s0 * d[e][1];
            xacc[2] += s0 * d[e][2];
            xacc[3] += s1 * d[e][3];
            xacc[4] += s1 * d[e][4];
            xacc[5] += s1 * d[e][5];
        }
    }

    // cross-warp reduction (block owns receiver r exclusively)
    atomicAdd(&sAgg[lane], agg0);
    atomicAdd(&sAgg[lane + 32], agg1);
    if (lane == 0) {
#pragma unroll
        for (int c = 0; c < 6; c++) atomicAdd(&sXu[c], xacc[c]);
    }
    __syncthreads();
    if (tid < HD) g_agg[r * HD + tid] = sAgg[tid];
    if (tid < 6) g_xupd[r * 6 + tid] = sXu[tid];
}

// ---------------- node update: h += silu([h,agg]@wh1+bh1)@wh2 + bh2 ; x += xupd/(T-1)
__global__ void k_update(const float* __restrict__ wh1,
                         const float* __restrict__ bh1,
                         const float* __restrict__ wh2,
                         const float* __restrict__ bh2, int layer) {
    const float* w1 = wh1 + layer * 128 * HD;
    const float* w2 = wh2 + layer * HD * HD;
    __shared__ float hs[HD], as[HD], us[HD];
    int t = blockIdx.x, j = threadIdx.x;
    hs[j] = g_h[t * HD + j];
    as[j] = g_agg[t * HD + j];
    __syncthreads();
    float u = bh1[layer * HD + j];
#pragma unroll 8
    for (int i = 0; i < HD; i++) u += hs[i] * w1[i * HD + j];
#pragma unroll 8
    for (int i = 0; i < HD; i++) u += as[i] * w1[(64 + i) * HD + j];
    us[j] = silu(u);
    __syncthreads();
    float o = bh2[layer * HD + j];
#pragma unroll 8
    for (int i = 0; i < HD; i++) o += us[i] * w2[i * HD + j];
    g_h[t * HD + j] = hs[j] + o;
    if (j < 6) g_x[t * 6 + j] += g_xupd[t * 6 + j] * INV_T1;
}

// ---------------- final: vectors = x - x0 ; scalars = h@w_head + b_head ----
__global__ void k_final(const float* __restrict__ pos,
                        const float* __restrict__ w_head,
                        const float* __restrict__ b_head,
                        float* __restrict__ out) {
    __shared__ float hs[HD];
    int t = blockIdx.x, j = threadIdx.x;
    hs[j] = g_h[t * HD + j];
    __syncthreads();
    float o = b_head[j];
#pragma unroll 8
    for (int i = 0; i < HD; i++) o += hs[i] * w_head[i * OUTD + j];
    out[VEC_OUT + t * OUTD + j] = o;
    if (j < 6) out[t * 6 + j] = g_x[t * 6 + j] - pos[t * 3 + (j % 3)];
}

// ---------------- launch ----------------
extern "C" void kernel_launch(void* const* d_in, const int* in_sizes, int n_in,
                              void* d_out, int out_size) {
    const float* positions = (const float*)d_in[0];   // [N,M,3]  = [768,3] flat
    const float* features  = (const float*)d_in[1];   // [768,32]
    const float* w_emb     = (const float*)d_in[2];   // [32,64]
    const float* b_emb     = (const float*)d_in[3];   // [64]
    const float* we1       = (const float*)d_in[4];   // [2,130,64]
    const float* be1       = (const float*)d_in[5];   // [2,64]
    const float* we2       = (const float*)d_in[6];   // [2,64,64]
    const float* be2       = (const float*)d_in[7];   // [2,64]
    const float* wx1       = (const float*)d_in[8];   // [2,64,64]
    const float* bx1       = (const float*)d_in[9];   // [2,64]
    const float* wx2       = (const float*)d_in[10];  // [2,64,2]
    const float* wh1       = (const float*)d_in[11];  // [2,128,64]
    const float* bh1       = (const float*)d_in[12];  // [2,64]
    const float* wh2       = (const float*)d_in[13];  // [2,64,64]
    const float* bh2       = (const float*)d_in[14];  // [2,64]
    const float* w_head    = (const float*)d_in[15];  // [64,64]
    const float* b_head    = (const float*)d_in[16];  // [64]
    float* out = (float*)d_out;

    k_init<<<NT, HD>>>(features, w_emb, b_emb, positions);
    for (int l = 0; l < LL; l++) {
        k_pre<<<NT, HD>>>(we1, be1, l);
        k_edge<<<NT, 256>>>(we1, we2, be2, wx1, bx1, wx2, l);
        k_update<<<NT, HD>>>(wh1, bh1, wh2, bh2, l);
    }
    k_final<<<NT, HD>>>(positions, w_head, b_head, out);
}

// round 4
// speedup vs baseline: 2.2002x; 2.2002x over previous
#include <cuda_runtime.h>
#include <math.h>

#define NT   768
#define HD   64
#define FD   32
#define LL   2
#define OUTD 64
#define VEC_OUT (NT * 6)
#define INV_T1 (1.0f / 767.0f)
#define EPT   16          // edges per warp per pass
#define PITCH 18          // t-tile row pitch (floats)

typedef unsigned long long ull;

// ---------------- device scratch ----------------
__device__ float  g_h[NT * HD];
__device__ float  g_x8[NT * 8];       // padded x_vec rows: [0..5]=x, [6..7]=pad
__device__ float2 g_A2[NT * 32];      // (A[c], A[c+32]) pairs
__device__ float2 g_B2[NT * 32];      // (B[c], B[c+32]) pairs (incl. be1)
__device__ float  g_agg[NT * HD];
__device__ float  g_xupd[NT * 6];

__device__ __forceinline__ float silu(float x) {
    return x * __fdividef(1.0f, 1.0f + __expf(-x));
}
__device__ __forceinline__ ull ffma2(ull a, ull b, ull c) {
    ull d; asm("fma.rn.f32x2 %0, %1, %2, %3;" : "=l"(d) : "l"(a), "l"(b), "l"(c));
    return d;
}
__device__ __forceinline__ ull dup2(float x) {
    ull d; asm("mov.b64 %0, {%1, %1};" : "=l"(d) : "f"(x)); return d;
}
__device__ __forceinline__ void unp(ull v, float& lo, float& hi) {
    asm("mov.b64 {%0, %1}, %2;" : "=f"(lo), "=f"(hi) : "l"(v));
}

// ---------------- init: h = feat@w_emb + b ; x ; A/B for layer 0 ----------
__global__ void k_init(const float* __restrict__ feat,
                       const float* __restrict__ w_emb,
                       const float* __restrict__ b_emb,
                       const float* __restrict__ pos,
                       const float* __restrict__ we1,
                       const float* __restrict__ be1) {
    __shared__ float fs[4][FD], hs[4][HD];
    int g = threadIdx.x >> 6, j = threadIdx.x & 63;
    int t = blockIdx.x * 4 + g;
    if (j < FD) fs[g][j] = feat[t * FD + j];
    __syncthreads();
    float acc = b_emb[j];
#pragma unroll
    for (int i = 0; i < FD; i++) acc += fs[g][i] * w_emb[i * HD + j];
    g_h[t * HD + j] = acc;
    hs[g][j] = acc;
    if (j < 8) g_x8[t * 8 + j] = (j < 6) ? pos[t * 3 + (j % 3)] : 0.0f;
    __syncthreads();
    if (j < 32) {
        const float* w = we1;                 // layer 0
        float alo = 0, ahi = 0;
        float blo = be1[j], bhi = be1[j + 32];
#pragma unroll 8
        for (int i = 0; i < HD; i++) {
            float hv = hs[g][i];
            alo += hv * w[i * HD + j];
            ahi += hv * w[i * HD + j + 32];
            blo += hv * w[(64 + i) * HD + j];
            bhi += hv * w[(64 + i) * HD + j + 32];
        }
        g_A2[t * 32 + j] = make_float2(alo, ahi);
        g_B2[t * 32 + j] = make_float2(blo, bhi);
    }
}

// ---------------- edge kernel: one block per receiver, dynamic smem ------
__global__ void __launch_bounds__(256, 3) k_edge(
    const float* __restrict__ we1, const float* __restrict__ we2,
    const float* __restrict__ be2, const float* __restrict__ wx1,
    const float* __restrict__ bx1, const float* __restrict__ wx2,
    int layer) {
    const float* we1l = we1 + layer * 130 * HD;
    const float* we2l = we2 + layer * HD * HD;
    const float* wx1l = wx1 + layer * HD * HD;
    const float* wx2l = wx2 + layer * HD * 2;

    extern __shared__ float sm[];
    float2* sW2  = (float2*)sm;               // [64*32]  16KB
    float2* sWX  = sW2 + 2048;                // [64*32]  16KB
    float*  tAll = (float*)(sWX + 2048);      // 8 * 64*PITCH
    float*  sdAll = tAll + 8 * HD * PITCH;    // 8 * 16*8
    float*  sAgg = sdAll + 8 * 128;           // [64]
    float*  sXu  = sAgg + 64;                 // [6]

    const int r = blockIdx.x;
    const int tid = threadIdx.x;
    const int warp = tid >> 5, lane = tid & 31;
    float* tb  = tAll + warp * (HD * PITCH);
    float* sdb = sdAll + warp * 128;

    for (int idx = tid; idx < 2048; idx += 256) {
        int i = idx >> 5, j = idx & 31;
        sW2[idx] = make_float2(we2l[i * HD + j], we2l[i * HD + j + 32]);
        sWX[idx] = make_float2(wx1l[i * HD + j], wx1l[i * HD + j + 32]);
    }
    if (tid < 64) sAgg[tid] = 0.0f;
    if (tid < 6) sXu[tid] = 0.0f;
    __syncthreads();

    // hoisted per-lane constants
    const float2 Cr = g_B2[r * 32 + lane];
    const float wq00 = we1l[128 * HD + lane], wq01 = we1l[128 * HD + lane + 32];
    const float wq10 = we1l[129 * HD + lane], wq11 = we1l[129 * HD + lane + 32];
    const float bb20 = be2[layer * HD + lane], bb21 = be2[layer * HD + lane + 32];
    const float bxl0 = bx1[layer * HD + lane], bxl1 = bx1[layer * HD + lane + 32];
    const float2 wx2a = ((const float2*)wx2l)[lane];
    const float2 wx2b = ((const float2*)wx2l)[lane + 32];
    const float4 xra = *(const float4*)&g_x8[r * 8];
    const float4 xrb = *(const float4*)&g_x8[r * 8 + 4];

    float agg0 = 0.0f, agg1 = 0.0f;
    float xacc[6] = {0, 0, 0, 0, 0, 0};

    for (int s0 = warp * EPT; s0 < NT; s0 += 8 * EPT) {
        // ---- prologue: edge-owner lanes compute diffs/scales ----
        if (lane < 16) {
            int s = s0 + lane;
            const float4* xp = (const float4*)&g_x8[s * 8];
            float4 xa = __ldg(xp), xb = __ldg(xp + 1);
            float d0 = xa.x - xra.x, d1 = xa.y - xra.y, d2 = xa.z - xra.z;
            float d3 = xa.w - xra.w, d4 = xb.x - xrb.x, d5 = xb.y - xrb.y;
            float sq0 = d0 * d0 + d1 * d1 + d2 * d2;
            float sq1 = d3 * d3 + d4 * d4 + d5 * d5;
            float r0 = __fdividef(1.0f, __fsqrt_rn(sq0 + 1e-8f) + 1.0f);
            float r1 = __fdividef(1.0f, __fsqrt_rn(sq1 + 1e-8f) + 1.0f);
            float4* o = (float4*)&sdb[lane * 8];
            o[0] = make_float4(d0 * r0, d1 * r0, d2 * r0, d3 * r1);
            o[1] = make_float4(d4 * r1, d5 * r1, sq0, sq1);
        }
        __syncwarp();

        // ---- t fill: t = silu(A[s] + B[r] + sq @ wq) -> tile [64][EPT] ----
#pragma unroll 4
        for (int e = 0; e < EPT; e++) {
            int s = s0 + e;
            float2 qq = *(const float2*)&sdb[e * 8 + 6];
            float2 a = __ldg(&g_A2[s * 32 + lane]);
            float p0 = a.x + Cr.x + qq.x * wq00 + qq.y * wq10;
            float p1 = a.y + Cr.y + qq.x * wq01 + qq.y * wq11;
            tb[lane * PITCH + e] = silu(p0);
            tb[(lane + 32) * PITCH + e] = silu(p1);
        }
        __syncwarp();

        // ---- matmul 1: m_pre = t @ we2 + be2 (packed edge pairs) ----
        ull accL[8], accH[8];
        {
            ull bL = dup2(bb20), bH = dup2(bb21);
#pragma unroll
            for (int p = 0; p < 8; p++) { accL[p] = bL; accH[p] = bH; }
        }
#pragma unroll 8
        for (int i = 0; i < HD; i++) {
            float2 w = sW2[i * 32 + lane];
            ull wl = dup2(w.x), wh = dup2(w.y);
            const ull* ar = (const ull*)&tb[i * PITCH];
#pragma unroll
            for (int p = 0; p < 8; p++) {
                ull a = ar[p];
                accL[p] = ffma2(a, wl, accL[p]);
                accH[p] = ffma2(a, wh, accH[p]);
            }
        }
        __syncwarp();

        // ---- m = silu(m_pre) * mask ; agg ; store m into tile ----
#pragma unroll
        for (int p = 0; p < 8; p++) {
            float mA, mB, nA, nB;
            unp(accL[p], mA, mB);
            unp(accH[p], nA, nB);
            int sA = s0 + 2 * p;
            float k0 = (sA != r) ? 1.0f : 0.0f;
            float k1 = (sA + 1 != r) ? 1.0f : 0.0f;
            mA = silu(mA) * k0; mB = silu(mB) * k1;
            nA = silu(nA) * k0; nB = silu(nB) * k1;
            agg0 += mA + mB; agg1 += nA + nB;
            *(float2*)&tb[lane * PITCH + 2 * p] = make_float2(mA, mB);
            *(float2*)&tb[(lane + 32) * PITCH + 2 * p] = make_float2(nA, nB);
        }
        __syncwarp();

        // ---- matmul 2: p_pre = m @ wx1 + bx1 ----
        {
            ull bL = dup2(bxl0), bH = dup2(bxl1);
#pragma unroll
            for (int p = 0; p < 8; p++) { accL[p] = bL; accH[p] = bH; }
        }
#pragma unroll 8
        for (int i = 0; i < HD; i++) {
            float2 w = sWX[i * 32 + lane];
            ull wl = dup2(w.x), wh = dup2(w.y);
            const ull* ar = (const ull*)&tb[i * PITCH];
#pragma unroll
            for (int p = 0; p < 8; p++) {
                ull a = ar[p];
                accL[p] = ffma2(a, wl, accL[p]);
                accH[p] = ffma2(a, wh, accH[p]);
            }
        }

        // ---- epilogue: q = silu(p); per-lane phi partial x sd ----
#pragma unroll
        for (int p = 0; p < 8; p++) {
            float pA, pB, nA, nB;
            unp(accL[p], pA, pB);
            unp(accH[p], nA, nB);
            {   // edge 2p
                float q0 = silu(pA), q1 = silu(nA);
                float ph0 = q0 * wx2a.x + q1 * wx2b.x;
                float ph1 = q0 * wx2a.y + q1 * wx2b.y;
                const float4* sd = (const float4*)&sdb[(2 * p) * 8];
                float4 s0v = sd[0], s1v = sd[1];
                xacc[0] += ph0 * s0v.x; xacc[1] += ph0 * s0v.y; xacc[2] += ph0 * s0v.z;
                xacc[3] += ph1 * s0v.w; xacc[4] += ph1 * s1v.x; xacc[5] += ph1 * s1v.y;
            }
            {   // edge 2p+1
                float q0 = silu(pB), q1 = silu(nB);
                float ph0 = q0 * wx2a.x + q1 * wx2b.x;
                float ph1 = q0 * wx2a.y + q1 * wx2b.y;
                const float4* sd = (const float4*)&sdb[(2 * p + 1) * 8];
                float4 s0v = sd[0], s1v = sd[1];
                xacc[0] += ph0 * s0v.x; xacc[1] += ph0 * s0v.y; xacc[2] += ph0 * s0v.z;
                xacc[3] += ph1 * s0v.w; xacc[4] += ph1 * s1v.x; xacc[5] += ph1 * s1v.y;
            }
        }
        __syncwarp();   // protect sdb before next prologue
    }

    // ---- reductions ----
#pragma unroll
    for (int off = 16; off > 0; off >>= 1) {
#pragma unroll
        for (int c = 0; c < 6; c++)
            xacc[c] += __shfl_xor_sync(0xffffffffu, xacc[c], off);
    }
    if (lane == 0) {
#pragma unroll
        for (int c = 0; c < 6; c++) atomicAdd(&sXu[c], xacc[c]);
    }
    atomicAdd(&sAgg[lane], agg0);
    atomicAdd(&sAgg[lane + 32], agg1);
    __syncthreads();
    if (tid < 64) g_agg[r * HD + tid] = sAgg[tid];
    if (tid < 6) g_xupd[r * 6 + tid] = sXu[tid];
}

// ---------------- node update (+ fused A/B precompute for next layer) ----
__global__ void k_update(const float* __restrict__ wh1,
                         const float* __restrict__ bh1,
                         const float* __restrict__ wh2,
                         const float* __restrict__ bh2,
                         const float* __restrict__ we1,
                         const float* __restrict__ be1,
                         int layer, int next_layer) {
    __shared__ float hs[4][HD], as[4][HD], us[4][HD];
    int g = threadIdx.x >> 6, j = threadIdx.x & 63;
    int t = blockIdx.x * 4 + g;
    const float* w1 = wh1 + layer * 128 * HD;
    const float* w2 = wh2 + layer * HD * HD;
    hs[g][j] = g_h[t * HD + j];
    as[g][j] = g_agg[t * HD + j];
    __syncthreads();
    float u = bh1[layer * HD + j];
#pragma unroll 8
    for (int i = 0; i < HD; i++) u += hs[g][i] * w1[i * HD + j];
#pragma unroll 8
    for (int i = 0; i < HD; i++) u += as[g][i] * w1[(64 + i) * HD + j];
    us[g][j] = silu(u);
    __syncthreads();
    float o = bh2[layer * HD + j];
#pragma unroll 8
    for (int i = 0; i < HD; i++) o += us[g][i] * w2[i * HD + j];
    float hn = hs[g][j] + o;
    g_h[t * HD + j] = hn;
    if (j < 6) g_x8[t * 8 + j] += g_xupd[t * 6 + j] * INV_T1;
    if (next_layer < LL) {
        hs[g][j] = hn;          // own element only -> safe before barrier
        __syncthreads();
        const float* w = we1 + next_layer * 130 * HD;
        if (j < 32) {
            float alo = 0, ahi = 0;
            float blo = be1[next_layer * HD + j], bhi = be1[next_layer * HD + j + 32];
#pragma unroll 8
            for (int i = 0; i < HD; i++) {
                float hv = hs[g][i];
                alo += hv * w[i * HD + j];
                ahi += hv * w[i * HD + j + 32];
                blo += hv * w[(64 + i) * HD + j];
                bhi += hv * w[(64 + i) * HD + j + 32];
            }
            g_A2[t * 32 + j] = make_float2(alo, ahi);
            g_B2[t * 32 + j] = make_float2(blo, bhi);
        }
    }
}

// ---------------- final head ----------------
__global__ void k_final(const float* __restrict__ pos,
                        const float* __restrict__ w_head,
                        const float* __restrict__ b_head,
                        float* __restrict__ out) {
    __shared__ float hs[4][HD];
    int g = threadIdx.x >> 6, j = threadIdx.x & 63;
    int t = blockIdx.x * 4 + g;
    hs[g][j] = g_h[t * HD + j];
    __syncthreads();
    float o = b_head[j];
#pragma unroll 8
    for (int i = 0; i < HD; i++) o += hs[g][i] * w_head[i * OUTD + j];
    out[VEC_OUT + t * OUTD + j] = o;
    if (j < 6) out[t * 6 + j] = g_x8[t * 8 + j] - pos[t * 3 + (j % 3)];
}

// ---------------- launch ----------------
#define EDGE_SMEM (2048*8*2 + 8*HD*PITCH*4 + 8*128*4 + 64*4 + 6*4)

extern "C" void kernel_launch(void* const* d_in, const int* in_sizes, int n_in,
                              void* d_out, int out_size) {
    const float* positions = (const float*)d_in[0];
    const float* features  = (const float*)d_in[1];
    const float* w_emb     = (const float*)d_in[2];
    const float* b_emb     = (const float*)d_in[3];
    const float* we1       = (const float*)d_in[4];
    const float* be1       = (const float*)d_in[5];
    const float* we2       = (const float*)d_in[6];
    const float* be2       = (const float*)d_in[7];
    const float* wx1       = (const float*)d_in[8];
    const float* bx1       = (const float*)d_in[9];
    const float* wx2       = (const float*)d_in[10];
    const float* wh1       = (const float*)d_in[11];
    const float* bh1       = (const float*)d_in[12];
    const float* wh2       = (const float*)d_in[13];
    const float* bh2       = (const float*)d_in[14];
    const float* w_head    = (const float*)d_in[15];
    const float* b_head    = (const float*)d_in[16];
    float* out = (float*)d_out;

    cudaFuncSetAttribute(k_edge, cudaFuncAttributeMaxDynamicSharedMemorySize,
                         EDGE_SMEM);

    k_init<<<NT / 4, 256>>>(features, w_emb, b_emb, positions, we1, be1);
    for (int l = 0; l < LL; l++) {
        k_edge<<<NT, 256, EDGE_SMEM>>>(we1, we2, be2, wx1, bx1, wx2, l);
        k_update<<<NT / 4, 256>>>(wh1, bh1, wh2, bh2, we1, be1, l, l + 1);
    }
    k_final<<<NT / 4, 256>>>(positions, w_head, b_head, out);
}

// round 5
// speedup vs baseline: 2.2171x; 1.0077x over previous
#include <cuda_runtime.h>
#include <math.h>

#define NT   768
#define HD   64
#define FD   32
#define LL   2
#define OUTD 64
#define VEC_OUT (NT * 6)
#define INV_T1 (1.0f / 767.0f)
#define EPT   16          // edges per warp per pass

typedef unsigned long long ull;

// ---------------- device scratch ----------------
__device__ float  g_h[NT * HD];
__device__ float  g_x8[NT * 8];       // padded x_vec rows: [0..5]=x, [6..7]=pad
__device__ float2 g_A2[NT * 32];      // (A[c], A[c+32]) pairs
__device__ float2 g_B2[NT * 32];      // (B[c], B[c+32]) pairs (incl. be1)
__device__ float  g_agg[NT * HD];
__device__ float  g_xupd[NT * 6];

__device__ __forceinline__ float silu(float x) {
    return x * __fdividef(1.0f, 1.0f + __expf(-x));
}
__device__ __forceinline__ ull ffma2(ull a, ull b, ull c) {
    ull d; asm("fma.rn.f32x2 %0, %1, %2, %3;" : "=l"(d) : "l"(a), "l"(b), "l"(c));
    return d;
}
__device__ __forceinline__ ull dup2(float x) {
    ull d; asm("mov.b64 %0, {%1, %1};" : "=l"(d) : "f"(x)); return d;
}
__device__ __forceinline__ ull pack2(float lo, float hi) {
    ull d; asm("mov.b64 %0, {%1, %2};" : "=l"(d) : "f"(lo), "f"(hi)); return d;
}
__device__ __forceinline__ void unp(ull v, float& lo, float& hi) {
    asm("mov.b64 {%0, %1}, %2;" : "=f"(lo), "=f"(hi) : "l"(v));
}

// ---------------- init: h = feat@w_emb + b ; x ; A/B for layer 0 ----------
__global__ void k_init(const float* __restrict__ feat,
                       const float* __restrict__ w_emb,
                       const float* __restrict__ b_emb,
                       const float* __restrict__ pos,
                       const float* __restrict__ we1,
                       const float* __restrict__ be1) {
    __shared__ float fs[4][FD], hs[4][HD];
    int g = threadIdx.x >> 6, j = threadIdx.x & 63;
    int t = blockIdx.x * 4 + g;
    if (j < FD) fs[g][j] = feat[t * FD + j];
    __syncthreads();
    float acc = b_emb[j];
#pragma unroll
    for (int i = 0; i < FD; i++) acc += fs[g][i] * w_emb[i * HD + j];
    g_h[t * HD + j] = acc;
    hs[g][j] = acc;
    if (j < 8) g_x8[t * 8 + j] = (j < 6) ? pos[t * 3 + (j % 3)] : 0.0f;
    __syncthreads();
    if (j < 32) {
        const float* w = we1;                 // layer 0
        float alo = 0, ahi = 0;
        float blo = be1[j], bhi = be1[j + 32];
#pragma unroll 8
        for (int i = 0; i < HD; i++) {
            float hv = hs[g][i];
            alo += hv * w[i * HD + j];
            ahi += hv * w[i * HD + j + 32];
            blo += hv * w[(64 + i) * HD + j];
            bhi += hv * w[(64 + i) * HD + j + 32];
        }
        g_A2[t * 32 + j] = make_float2(alo, ahi);
        g_B2[t * 32 + j] = make_float2(blo, bhi);
    }
}

// ---------------- edge kernel: one block per receiver ----------------
// Tile layout: tq[p][i] (p = edge-pair 0..7, i = channel 0..63), each entry
// a packed ull (edge 2p, edge 2p+1). Rows are 512B -> LDS.128 broadcasts.
__global__ void __launch_bounds__(256, 3) k_edge(
    const float* __restrict__ we1, const float* __restrict__ we2,
    const float* __restrict__ be2, const float* __restrict__ wx1,
    const float* __restrict__ bx1, const float* __restrict__ wx2,
    int layer) {
    const float* we1l = we1 + layer * 130 * HD;
    const float* we2l = we2 + layer * HD * HD;
    const float* wx1l = wx1 + layer * HD * HD;
    const float* wx2l = wx2 + layer * HD * 2;

    extern __shared__ float sm[];
    float4* sW2q  = (float4*)sm;              // [32*32] 16KB: (w[2i][c],w[2i][c+32],w[2i+1][c],w[2i+1][c+32])
    float4* sWXq  = sW2q + 1024;              // 16KB
    ull*    tAll  = (ull*)(sWXq + 1024);      // 8 warps * 8 rows * 64 ull = 32KB
    float*  sdAll = (float*)(tAll + 4096);    // 8 * 128 floats = 4KB
    float*  sAgg  = sdAll + 1024;             // [64]
    float*  sXu   = sAgg + 64;                // [6]

    const int r = blockIdx.x;
    const int tid = threadIdx.x;
    const int warp = tid >> 5, lane = tid & 31;
    ull*   tb  = tAll + warp * 512;           // row p at tb + p*64
    float* sdb = sdAll + warp * 128;

    for (int idx = tid; idx < 1024; idx += 256) {
        int i2 = idx >> 5, j = idx & 31;
        sW2q[idx] = make_float4(we2l[(2 * i2) * HD + j],     we2l[(2 * i2) * HD + j + 32],
                                we2l[(2 * i2 + 1) * HD + j], we2l[(2 * i2 + 1) * HD + j + 32]);
        sWXq[idx] = make_float4(wx1l[(2 * i2) * HD + j],     wx1l[(2 * i2) * HD + j + 32],
                                wx1l[(2 * i2 + 1) * HD + j], wx1l[(2 * i2 + 1) * HD + j + 32]);
    }
    if (tid < 64) sAgg[tid] = 0.0f;
    if (tid < 6) sXu[tid] = 0.0f;
    __syncthreads();

    // hoisted per-lane constants (lane owns channels lane, lane+32)
    const float2 Cr = g_B2[r * 32 + lane];
    const float wq00 = we1l[128 * HD + lane], wq01 = we1l[128 * HD + lane + 32];
    const float wq10 = we1l[129 * HD + lane], wq11 = we1l[129 * HD + lane + 32];
    const float bb20 = be2[layer * HD + lane], bb21 = be2[layer * HD + lane + 32];
    const float bxl0 = bx1[layer * HD + lane], bxl1 = bx1[layer * HD + lane + 32];
    const float2 wx2a = ((const float2*)wx2l)[lane];
    const float2 wx2b = ((const float2*)wx2l)[lane + 32];
    const float4 xra = *(const float4*)&g_x8[r * 8];
    const float4 xrb = *(const float4*)&g_x8[r * 8 + 4];

    float agg0 = 0.0f, agg1 = 0.0f;
    float xacc[6] = {0, 0, 0, 0, 0, 0};

    for (int s0 = warp * EPT; s0 < NT; s0 += 8 * EPT) {
        // ---- prologue: edge-owner lanes compute diffs/scales ----
        if (lane < 16) {
            int s = s0 + lane;
            const float4* xp = (const float4*)&g_x8[s * 8];
            float4 xa = __ldg(xp), xb = __ldg(xp + 1);
            float d0 = xa.x - xra.x, d1 = xa.y - xra.y, d2 = xa.z - xra.z;
            float d3 = xa.w - xra.w, d4 = xb.x - xrb.x, d5 = xb.y - xrb.y;
            float sq0 = d0 * d0 + d1 * d1 + d2 * d2;
            float sq1 = d3 * d3 + d4 * d4 + d5 * d5;
            float r0 = __fdividef(1.0f, __fsqrt_rn(sq0 + 1e-8f) + 1.0f);
            float r1 = __fdividef(1.0f, __fsqrt_rn(sq1 + 1e-8f) + 1.0f);
            float4* o = (float4*)&sdb[lane * 8];
            o[0] = make_float4(d0 * r0, d1 * r0, d2 * r0, d3 * r1);
            o[1] = make_float4(d4 * r1, d5 * r1, sq0, sq1);
        }
        __syncwarp();

        // ---- t fill: t = silu(A[s] + B[r] + sq @ wq), packed edge pairs ----
#pragma unroll
        for (int p = 0; p < 8; p++) {
            int s = s0 + 2 * p;
            float2 qqA = *(const float2*)&sdb[(2 * p) * 8 + 6];
            float2 qqB = *(const float2*)&sdb[(2 * p + 1) * 8 + 6];
            float2 aA = __ldg(&g_A2[s * 32 + lane]);
            float2 aB = __ldg(&g_A2[(s + 1) * 32 + lane]);
            float pA0 = aA.x + Cr.x + qqA.x * wq00 + qqA.y * wq10;
            float pA1 = aA.y + Cr.y + qqA.x * wq01 + qqA.y * wq11;
            float pB0 = aB.x + Cr.x + qqB.x * wq00 + qqB.y * wq10;
            float pB1 = aB.y + Cr.y + qqB.x * wq01 + qqB.y * wq11;
            tb[p * 64 + lane]      = pack2(silu(pA0), silu(pB0));
            tb[p * 64 + lane + 32] = pack2(silu(pA1), silu(pB1));
        }
        __syncwarp();

        // ---- matmul 1: m_pre = t @ we2 + be2 ----
        ull accL[8], accH[8];
        {
            ull bL = dup2(bb20), bH = dup2(bb21);
#pragma unroll
            for (int p = 0; p < 8; p++) { accL[p] = bL; accH[p] = bH; }
        }
#pragma unroll 8
        for (int i2 = 0; i2 < 32; i2++) {
            float4 w = sW2q[i2 * 32 + lane];
            ull w00 = dup2(w.x), w01 = dup2(w.y), w10 = dup2(w.z), w11 = dup2(w.w);
            const ulonglong2* tp = (const ulonglong2*)(tb + 2 * i2);
#pragma unroll
            for (int q = 0; q < 8; q++) {
                ulonglong2 a = tp[q * 32];      // row q, channels 2*i2, 2*i2+1
                accL[q] = ffma2(a.x, w00, accL[q]);
                accH[q] = ffma2(a.x, w01, accH[q]);
                accL[q] = ffma2(a.y, w10, accL[q]);
                accH[q] = ffma2(a.y, w11, accH[q]);
            }
        }
        __syncwarp();   // all tile reads done before overwrite

        // ---- m = silu(m_pre) * mask ; agg ; store m into tile ----
#pragma unroll
        for (int p = 0; p < 8; p++) {
            float mA, mB, nA, nB;
            unp(accL[p], mA, mB);
            unp(accH[p], nA, nB);
            int sA = s0 + 2 * p;
            float k0 = (sA != r) ? 1.0f : 0.0f;
            float k1 = (sA + 1 != r) ? 1.0f : 0.0f;
            mA = silu(mA) * k0; mB = silu(mB) * k1;
            nA = silu(nA) * k0; nB = silu(nB) * k1;
            agg0 += mA + mB; agg1 += nA + nB;
            tb[p * 64 + lane]      = pack2(mA, mB);
            tb[p * 64 + lane + 32] = pack2(nA, nB);
        }
        __syncwarp();

        // ---- matmul 2: p_pre = m @ wx1 + bx1 ----
        {
            ull bL = dup2(bxl0), bH = dup2(bxl1);
#pragma unroll
            for (int p = 0; p < 8; p++) { accL[p] = bL; accH[p] = bH; }
        }
#pragma unroll 8
        for (int i2 = 0; i2 < 32; i2++) {
            float4 w = sWXq[i2 * 32 + lane];
            ull w00 = dup2(w.x), w01 = dup2(w.y), w10 = dup2(w.z), w11 = dup2(w.w);
            const ulonglong2* tp = (const ulonglong2*)(tb + 2 * i2);
#pragma unroll
            for (int q = 0; q < 8; q++) {
                ulonglong2 a = tp[q * 32];
                accL[q] = ffma2(a.x, w00, accL[q]);
                accH[q] = ffma2(a.x, w01, accH[q]);
                accL[q] = ffma2(a.y, w10, accL[q]);
                accH[q] = ffma2(a.y, w11, accH[q]);
            }
        }

        // ---- epilogue: q = silu(p); per-lane phi partial x sd ----
#pragma unroll
        for (int p = 0; p < 8; p++) {
            float pA, pB, nA, nB;
            unp(accL[p], pA, pB);
            unp(accH[p], nA, nB);
            {   // edge 2p
                float q0 = silu(pA), q1 = silu(nA);
                float ph0 = q0 * wx2a.x + q1 * wx2b.x;
                float ph1 = q0 * wx2a.y + q1 * wx2b.y;
                const float4* sd = (const float4*)&sdb[(2 * p) * 8];
                float4 s0v = sd[0], s1v = sd[1];
                xacc[0] += ph0 * s0v.x; xacc[1] += ph0 * s0v.y; xacc[2] += ph0 * s0v.z;
                xacc[3] += ph1 * s0v.w; xacc[4] += ph1 * s1v.x; xacc[5] += ph1 * s1v.y;
            }
            {   // edge 2p+1
                float q0 = silu(pB), q1 = silu(nB);
                float ph0 = q0 * wx2a.x + q1 * wx2b.x;
                float ph1 = q0 * wx2a.y + q1 * wx2b.y;
                const float4* sd = (const float4*)&sdb[(2 * p + 1) * 8];
                float4 s0v = sd[0], s1v = sd[1];
                xacc[0] += ph0 * s0v.x; xacc[1] += ph0 * s0v.y; xacc[2] += ph0 * s0v.z;
                xacc[3] += ph1 * s0v.w; xacc[4] += ph1 * s1v.x; xacc[5] += ph1 * s1v.y;
            }
        }
        __syncwarp();   // protect sdb & tile before next pass
    }

    // ---- reductions ----
#pragma unroll
    for (int off = 16; off > 0; off >>= 1) {
#pragma unroll
        for (int c = 0; c < 6; c++)
            xacc[c] += __shfl_xor_sync(0xffffffffu, xacc[c], off);
    }
    if (lane == 0) {
#pragma unroll
        for (int c = 0; c < 6; c++) atomicAdd(&sXu[c], xacc[c]);
    }
    atomicAdd(&sAgg[lane], agg0);
    atomicAdd(&sAgg[lane + 32], agg1);
    __syncthreads();
    if (tid < 64) g_agg[r * HD + tid] = sAgg[tid];
    if (tid < 6) g_xupd[r * 6 + tid] = sXu[tid];
}

// ---------------- node update (+ fused A/B precompute for next layer) ----
__global__ void k_update(const float* __restrict__ wh1,
                         const float* __restrict__ bh1,
                         const float* __restrict__ wh2,
                         const float* __restrict__ bh2,
                         const float* __restrict__ we1,
                         const float* __restrict__ be1,
                         int layer, int next_layer) {
    __shared__ float hs[4][HD], as[4][HD], us[4][HD];
    int g = threadIdx.x >> 6, j = threadIdx.x & 63;
    int t = blockIdx.x * 4 + g;
    const float* w1 = wh1 + layer * 128 * HD;
    const float* w2 = wh2 + layer * HD * HD;
    hs[g][j] = g_h[t * HD + j];
    as[g][j] = g_agg[t * HD + j];
    __syncthreads();
    float u = bh1[layer * HD + j];
#pragma unroll 8
    for (int i = 0; i < HD; i++) u += hs[g][i] * w1[i * HD + j];
#pragma unroll 8
    for (int i = 0; i < HD; i++) u += as[g][i] * w1[(64 + i) * HD + j];
    us[g][j] = silu(u);
    __syncthreads();
    float o = bh2[layer * HD + j];
#pragma unroll 8
    for (int i = 0; i < HD; i++) o += us[g][i] * w2[i * HD + j];
    float hn = hs[g][j] + o;
    g_h[t * HD + j] = hn;
    if (j < 6) g_x8[t * 8 + j] += g_xupd[t * 6 + j] * INV_T1;
    if (next_layer < LL) {
        hs[g][j] = hn;          // own element only -> safe before barrier
        __syncthreads();
        const float* w = we1 + next_layer * 130 * HD;
        if (j < 32) {
            float alo = 0, ahi = 0;
            float blo = be1[next_layer * HD + j], bhi = be1[next_layer * HD + j + 32];
#pragma unroll 8
            for (int i = 0; i < HD; i++) {
                float hv = hs[g][i];
                alo += hv * w[i * HD + j];
                ahi += hv * w[i * HD + j + 32];
                blo += hv * w[(64 + i) * HD + j];
                bhi += hv * w[(64 + i) * HD + j + 32];
            }
            g_A2[t * 32 + j] = make_float2(alo, ahi);
            g_B2[t * 32 + j] = make_float2(blo, bhi);
        }
    }
}

// ---------------- final head ----------------
__global__ void k_final(const float* __restrict__ pos,
                        const float* __restrict__ w_head,
                        const float* __restrict__ b_head,
                        float* __restrict__ out) {
    __shared__ float hs[4][HD];
    int g = threadIdx.x >> 6, j = threadIdx.x & 63;
    int t = blockIdx.x * 4 + g;
    hs[g][j] = g_h[t * HD + j];
    __syncthreads();
    float o = b_head[j];
#pragma unroll 8
    for (int i = 0; i < HD; i++) o += hs[g][i] * w_head[i * OUTD + j];
    out[VEC_OUT + t * OUTD + j] = o;
    if (j < 6) out[t * 6 + j] = g_x8[t * 8 + j] - pos[t * 3 + (j % 3)];
}

// ---------------- launch ----------------
#define EDGE_SMEM (16384 + 16384 + 32768 + 4096 + 256 + 24)

extern "C" void kernel_launch(void* const* d_in, const int* in_sizes, int n_in,
                              void* d_out, int out_size) {
    const float* positions = (const float*)d_in[0];
    const float* features  = (const float*)d_in[1];
    const float* w_emb     = (const float*)d_in[2];
    const float* b_emb     = (const float*)d_in[3];
    const float* we1       = (const float*)d_in[4];
    const float* be1       = (const float*)d_in[5];
    const float* we2       = (const float*)d_in[6];
    const float* be2       = (const float*)d_in[7];
    const float* wx1       = (const float*)d_in[8];
    const float* bx1       = (const float*)d_in[9];
    const float* wx2       = (const float*)d_in[10];
    const float* wh1       = (const float*)d_in[11];
    const float* bh1       = (const float*)d_in[12];
    const float* wh2       = (const float*)d_in[13];
    const float* bh2       = (const float*)d_in[14];
    const float* w_head    = (const float*)d_in[15];
    const float* b_head    = (const float*)d_in[16];
    float* out = (float*)d_out;

    cudaFuncSetAttribute(k_edge, cudaFuncAttributeMaxDynamicSharedMemorySize,
                         EDGE_SMEM);

    k_init<<<NT / 4, 256>>>(features, w_emb, b_emb, positions, we1, be1);
    for (int l = 0; l < LL; l++) {
        k_edge<<<NT, 256, EDGE_SMEM>>>(we1, we2, be2, wx1, bx1, wx2, l);
        k_update<<<NT / 4, 256>>>(wh1, bh1, wh2, bh2, we1, be1, l, l + 1);
    }
    k_final<<<NT / 4, 256>>>(positions, w_head, b_head, out);
}

// round 6
// speedup vs baseline: 2.5209x; 1.1370x over previous
#include <cuda_runtime.h>
#include <math.h>

#define NT   768
#define HD   64
#define FD   32
#define LL   2
#define OUTD 64
#define VEC_OUT (NT * 6)
#define INV_T1 (1.0f / 767.0f)
#define EPT   16          // edges per warp per pass

typedef unsigned long long ull;

// ---------------- device scratch ----------------
__device__ float  g_h[NT * HD];
__device__ float  g_x8[NT * 8];       // padded x_vec rows: [0..5]=x, [6..7]=pad
__device__ float2 g_A2[NT * 32];      // (A[c], A[c+32]) pairs
__device__ float2 g_B2[NT * 32];      // (B[c], B[c+32]) pairs (incl. be1)
__device__ float  g_agg[NT * HD];
__device__ float  g_xupd[NT * 6];

// silu via tanh: x * (0.5*tanh(x/2) + 0.5) — 1 MUFU, short dep chain
__device__ __forceinline__ float silu(float x) {
    float t;
    asm("tanh.approx.f32 %0, %1;" : "=f"(t) : "f"(0.5f * x));
    return x * fmaf(0.5f, t, 0.5f);
}
__device__ __forceinline__ ull ffma2(ull a, ull b, ull c) {
    ull d; asm("fma.rn.f32x2 %0, %1, %2, %3;" : "=l"(d) : "l"(a), "l"(b), "l"(c));
    return d;
}
__device__ __forceinline__ ull dup2(float x) {
    ull d; asm("mov.b64 %0, {%1, %1};" : "=l"(d) : "f"(x)); return d;
}
__device__ __forceinline__ ull pack2(float lo, float hi) {
    ull d; asm("mov.b64 %0, {%1, %2};" : "=l"(d) : "f"(lo), "f"(hi)); return d;
}
__device__ __forceinline__ void unp(ull v, float& lo, float& hi) {
    asm("mov.b64 {%0, %1}, %2;" : "=f"(lo), "=f"(hi) : "l"(v));
}

// ---------------- init: h = feat@w_emb + b ; x ; A/B for layer 0 ----------
__global__ void k_init(const float* __restrict__ feat,
                       const float* __restrict__ w_emb,
                       const float* __restrict__ b_emb,
                       const float* __restrict__ pos,
                       const float* __restrict__ we1,
                       const float* __restrict__ be1) {
    __shared__ float fs[4][FD], hs[4][HD];
    int g = threadIdx.x >> 6, j = threadIdx.x & 63;
    int t = blockIdx.x * 4 + g;
    if (j < FD) fs[g][j] = feat[t * FD + j];
    __syncthreads();
    float acc = b_emb[j];
#pragma unroll
    for (int i = 0; i < FD; i++) acc += fs[g][i] * w_emb[i * HD + j];
    g_h[t * HD + j] = acc;
    hs[g][j] = acc;
    if (j < 8) g_x8[t * 8 + j] = (j < 6) ? pos[t * 3 + (j % 3)] : 0.0f;
    __syncthreads();
    if (j < 32) {
        const float* w = we1;                 // layer 0
        float alo = 0, ahi = 0;
        float blo = be1[j], bhi = be1[j + 32];
#pragma unroll 8
        for (int i = 0; i < HD; i++) {
            float hv = hs[g][i];
            alo += hv * w[i * HD + j];
            ahi += hv * w[i * HD + j + 32];
            blo += hv * w[(64 + i) * HD + j];
            bhi += hv * w[(64 + i) * HD + j + 32];
        }
        g_A2[t * 32 + j] = make_float2(alo, ahi);
        g_B2[t * 32 + j] = make_float2(blo, bhi);
    }
}

// ---------------- edge kernel: one block per receiver ----------------
__global__ void __launch_bounds__(256, 2) k_edge(
    const float* __restrict__ we1, const float* __restrict__ we2,
    const float* __restrict__ be2, const float* __restrict__ wx1,
    const float* __restrict__ bx1, const float* __restrict__ wx2,
    int layer) {
    const float* we1l = we1 + layer * 130 * HD;
    const float* we2l = we2 + layer * HD * HD;
    const float* wx1l = wx1 + layer * HD * HD;
    const float* wx2l = wx2 + layer * HD * 2;

    extern __shared__ float sm[];
    float4* sW2q  = (float4*)sm;              // [32*32] 16KB
    float4* sWXq  = sW2q + 1024;              // 16KB
    ull*    tAll  = (ull*)(sWXq + 1024);      // 8 warps * 512 ull = 32KB
    float*  sdAll = (float*)(tAll + 4096);    // 8 * 128 floats = 4KB
    float*  sAgg  = sdAll + 1024;             // [64]
    float*  sXu   = sAgg + 64;                // [6]

    const int r = blockIdx.x;
    const int tid = threadIdx.x;
    const int warp = tid >> 5, lane = tid & 31;
    ull*   tb  = tAll + warp * 512;           // row p at tb + p*64
    float* sdb = sdAll + warp * 128;

    for (int idx = tid; idx < 1024; idx += 256) {
        int i2 = idx >> 5, j = idx & 31;
        sW2q[idx] = make_float4(we2l[(2 * i2) * HD + j],     we2l[(2 * i2) * HD + j + 32],
                                we2l[(2 * i2 + 1) * HD + j], we2l[(2 * i2 + 1) * HD + j + 32]);
        sWXq[idx] = make_float4(wx1l[(2 * i2) * HD + j],     wx1l[(2 * i2) * HD + j + 32],
                                wx1l[(2 * i2 + 1) * HD + j], wx1l[(2 * i2 + 1) * HD + j + 32]);
    }
    if (tid < 64) sAgg[tid] = 0.0f;
    if (tid < 6) sXu[tid] = 0.0f;
    __syncthreads();

    // hoisted per-lane constants (lane owns channels lane, lane+32)
    const float2 Cr = g_B2[r * 32 + lane];
    const float wq00 = we1l[128 * HD + lane], wq01 = we1l[128 * HD + lane + 32];
    const float wq10 = we1l[129 * HD + lane], wq11 = we1l[129 * HD + lane + 32];
    const float bb20 = be2[layer * HD + lane], bb21 = be2[layer * HD + lane + 32];
    const float bxl0 = bx1[layer * HD + lane], bxl1 = bx1[layer * HD + lane + 32];
    const float2 wx2a = ((const float2*)wx2l)[lane];
    const float2 wx2b = ((const float2*)wx2l)[lane + 32];
    const float4 xra = *(const float4*)&g_x8[r * 8];
    const float4 xrb = *(const float4*)&g_x8[r * 8 + 4];

    float agg0 = 0.0f, agg1 = 0.0f;
    float xacc[6] = {0, 0, 0, 0, 0, 0};

    for (int s0 = warp * EPT; s0 < NT; s0 += 8 * EPT) {
        // ---- prologue: edge-owner lanes compute diffs/scales ----
        if (lane < 16) {
            int s = s0 + lane;
            const float4* xp = (const float4*)&g_x8[s * 8];
            float4 xa = __ldg(xp), xb = __ldg(xp + 1);
            float d0 = xa.x - xra.x, d1 = xa.y - xra.y, d2 = xa.z - xra.z;
            float d3 = xa.w - xra.w, d4 = xb.x - xrb.x, d5 = xb.y - xrb.y;
            float sq0 = d0 * d0 + d1 * d1 + d2 * d2;
            float sq1 = d3 * d3 + d4 * d4 + d5 * d5;
            float r0 = __fdividef(1.0f, __fsqrt_rn(sq0 + 1e-8f) + 1.0f);
            float r1 = __fdividef(1.0f, __fsqrt_rn(sq1 + 1e-8f) + 1.0f);
            float4* o = (float4*)&sdb[lane * 8];
            o[0] = make_float4(d0 * r0, d1 * r0, d2 * r0, d3 * r1);
            o[1] = make_float4(d4 * r1, d5 * r1, sq0, sq1);
        }
        __syncwarp();

        // ---- t fill: t = silu(A[s] + B[r] + sq @ wq), packed edge pairs ----
#pragma unroll
        for (int p = 0; p < 8; p++) {
            int s = s0 + 2 * p;
            float2 qqA = *(const float2*)&sdb[(2 * p) * 8 + 6];
            float2 qqB = *(const float2*)&sdb[(2 * p + 1) * 8 + 6];
            float2 aA = __ldg(&g_A2[s * 32 + lane]);
            float2 aB = __ldg(&g_A2[(s + 1) * 32 + lane]);
            float pA0 = aA.x + Cr.x + qqA.x * wq00 + qqA.y * wq10;
            float pA1 = aA.y + Cr.y + qqA.x * wq01 + qqA.y * wq11;
            float pB0 = aB.x + Cr.x + qqB.x * wq00 + qqB.y * wq10;
            float pB1 = aB.y + Cr.y + qqB.x * wq01 + qqB.y * wq11;
            tb[p * 64 + lane]      = pack2(silu(pA0), silu(pB0));
            tb[p * 64 + lane + 32] = pack2(silu(pA1), silu(pB1));
        }
        __syncwarp();

        // ---- matmul 1: m_pre = t @ we2 + be2 (prefetched operand stream) ----
        ull accL[8], accH[8];
        {
            ull bL = dup2(bb20), bH = dup2(bb21);
#pragma unroll
            for (int p = 0; p < 8; p++) { accL[p] = bL; accH[p] = bH; }
        }
        {
            ulonglong2 a0[8];
#pragma unroll
            for (int q = 0; q < 8; q++) a0[q] = ((const ulonglong2*)tb)[q * 32];
#pragma unroll
            for (int i2 = 0; i2 < 32; i2++) {
                float4 w = sW2q[i2 * 32 + lane];
                ull w00 = dup2(w.x), w01 = dup2(w.y), w10 = dup2(w.z), w11 = dup2(w.w);
                ulonglong2 a1[8];
                if (i2 < 31) {
                    const ulonglong2* tp = (const ulonglong2*)(tb + 2 * (i2 + 1));
#pragma unroll
                    for (int q = 0; q < 8; q++) a1[q] = tp[q * 32];
                }
#pragma unroll
                for (int q = 0; q < 8; q++) {
                    accL[q] = ffma2(a0[q].x, w00, accL[q]);
                    accH[q] = ffma2(a0[q].x, w01, accH[q]);
                    accL[q] = ffma2(a0[q].y, w10, accL[q]);
                    accH[q] = ffma2(a0[q].y, w11, accH[q]);
                }
#pragma unroll
                for (int q = 0; q < 8; q++) a0[q] = a1[q];
            }
        }
        __syncwarp();   // all tile reads done before overwrite

        // ---- m = silu(m_pre) * mask ; agg ; store m into tile ----
#pragma unroll
        for (int p = 0; p < 8; p++) {
            float mA, mB, nA, nB;
            unp(accL[p], mA, mB);
            unp(accH[p], nA, nB);
            int sA = s0 + 2 * p;
            float k0 = (sA != r) ? 1.0f : 0.0f;
            float k1 = (sA + 1 != r) ? 1.0f : 0.0f;
            mA = silu(mA) * k0; mB = silu(mB) * k1;
            nA = silu(nA) * k0; nB = silu(nB) * k1;
            agg0 += mA + mB; agg1 += nA + nB;
            tb[p * 64 + lane]      = pack2(mA, mB);
            tb[p * 64 + lane + 32] = pack2(nA, nB);
        }
        __syncwarp();

        // ---- matmul 2: p_pre = m @ wx1 + bx1 ----
        {
            ull bL = dup2(bxl0), bH = dup2(bxl1);
#pragma unroll
            for (int p = 0; p < 8; p++) { accL[p] = bL; accH[p] = bH; }
        }
        {
            ulonglong2 a0[8];
#pragma unroll
            for (int q = 0; q < 8; q++) a0[q] = ((const ulonglong2*)tb)[q * 32];
#pragma unroll
            for (int i2 = 0; i2 < 32; i2++) {
                float4 w = sWXq[i2 * 32 + lane];
                ull w00 = dup2(w.x), w01 = dup2(w.y), w10 = dup2(w.z), w11 = dup2(w.w);
                ulonglong2 a1[8];
                if (i2 < 31) {
                    const ulonglong2* tp = (const ulonglong2*)(tb + 2 * (i2 + 1));
#pragma unroll
                    for (int q = 0; q < 8; q++) a1[q] = tp[q * 32];
                }
#pragma unroll
                for (int q = 0; q < 8; q++) {
                    accL[q] = ffma2(a0[q].x, w00, accL[q]);
                    accH[q] = ffma2(a0[q].x, w01, accH[q]);
                    accL[q] = ffma2(a0[q].y, w10, accL[q]);
                    accH[q] = ffma2(a0[q].y, w11, accH[q]);
                }
#pragma unroll
                for (int q = 0; q < 8; q++) a0[q] = a1[q];
            }
        }

        // ---- epilogue: q = silu(p); per-lane phi partial x sd ----
#pragma unroll
        for (int p = 0; p < 8; p++) {
            float pA, pB, nA, nB;
            unp(accL[p], pA, pB);
            unp(accH[p], nA, nB);
            {   // edge 2p
                float q0 = silu(pA), q1 = silu(nA);
                float ph0 = q0 * wx2a.x + q1 * wx2b.x;
                float ph1 = q0 * wx2a.y + q1 * wx2b.y;
                const float4* sd = (const float4*)&sdb[(2 * p) * 8];
                float4 s0v = sd[0], s1v = sd[1];
                xacc[0] += ph0 * s0v.x; xacc[1] += ph0 * s0v.y; xacc[2] += ph0 * s0v.z;
                xacc[3] += ph1 * s0v.w; xacc[4] += ph1 * s1v.x; xacc[5] += ph1 * s1v.y;
            }
            {   // edge 2p+1
                float q0 = silu(pB), q1 = silu(nB);
                float ph0 = q0 * wx2a.x + q1 * wx2b.x;
                float ph1 = q0 * wx2a.y + q1 * wx2b.y;
                const float4* sd = (const float4*)&sdb[(2 * p + 1) * 8];
                float4 s0v = sd[0], s1v = sd[1];
                xacc[0] += ph0 * s0v.x; xacc[1] += ph0 * s0v.y; xacc[2] += ph0 * s0v.z;
                xacc[3] += ph1 * s0v.w; xacc[4] += ph1 * s1v.x; xacc[5] += ph1 * s1v.y;
            }
        }
        __syncwarp();   // protect sdb & tile before next pass
    }

    // ---- reductions ----
#pragma unroll
    for (int off = 16; off > 0; off >>= 1) {
#pragma unroll
        for (int c = 0; c < 6; c++)
            xacc[c] += __shfl_xor_sync(0xffffffffu, xacc[c], off);
    }
    if (lane == 0) {
#pragma unroll
        for (int c = 0; c < 6; c++) atomicAdd(&sXu[c], xacc[c]);
    }
    atomicAdd(&sAgg[lane], agg0);
    atomicAdd(&sAgg[lane + 32], agg1);
    __syncthreads();
    if (tid < 64) g_agg[r * HD + tid] = sAgg[tid];
    if (tid < 6) g_xupd[r * 6 + tid] = sXu[tid];
}

// ---------------- node update (+ fused A/B precompute for next layer) ----
__global__ void k_update(const float* __restrict__ wh1,
                         const float* __restrict__ bh1,
                         const float* __restrict__ wh2,
                         const float* __restrict__ bh2,
                         const float* __restrict__ we1,
                         const float* __restrict__ be1,
                         int layer, int next_layer) {
    __shared__ float hs[4][HD], as[4][HD], us[4][HD];
    int g = threadIdx.x >> 6, j = threadIdx.x & 63;
    int t = blockIdx.x * 4 + g;
    const float* w1 = wh1 + layer * 128 * HD;
    const float* w2 = wh2 + layer * HD * HD;
    hs[g][j] = g_h[t * HD + j];
    as[g][j] = g_agg[t * HD + j];
    __syncthreads();
    float u = bh1[layer * HD + j];
#pragma unroll 8
    for (int i = 0; i < HD; i++) u += hs[g][i] * w1[i * HD + j];
#pragma unroll 8
    for (int i = 0; i < HD; i++) u += as[g][i] * w1[(64 + i) * HD + j];
    us[g][j] = silu(u);
    __syncthreads();
    float o = bh2[layer * HD + j];
#pragma unroll 8
    for (int i = 0; i < HD; i++) o += us[g][i] * w2[i * HD + j];
    float hn = hs[g][j] + o;
    g_h[t * HD + j] = hn;
    if (j < 6) g_x8[t * 8 + j] += g_xupd[t * 6 + j] * INV_T1;
    if (next_layer < LL) {
        hs[g][j] = hn;          // own element only -> safe before barrier
        __syncthreads();
        const float* w = we1 + next_layer * 130 * HD;
        if (j < 32) {
            float alo = 0, ahi = 0;
            float blo = be1[next_layer * HD + j], bhi = be1[next_layer * HD + j + 32];
#pragma unroll 8
            for (int i = 0; i < HD; i++) {
                float hv = hs[g][i];
                alo += hv * w[i * HD + j];
                ahi += hv * w[i * HD + j + 32];
                blo += hv * w[(64 + i) * HD + j];
                bhi += hv * w[(64 + i) * HD + j + 32];
            }
            g_A2[t * 32 + j] = make_float2(alo, ahi);
            g_B2[t * 32 + j] = make_float2(blo, bhi);
        }
    }
}

// ---------------- final head ----------------
__global__ void k_final(const float* __restrict__ pos,
                        const float* __restrict__ w_head,
                        const float* __restrict__ b_head,
                        float* __restrict__ out) {
    __shared__ float hs[4][HD];
    int g = threadIdx.x >> 6, j = threadIdx.x & 63;
    int t = blockIdx.x * 4 + g;
    hs[g][j] = g_h[t * HD + j];
    __syncthreads();
    float o = b_head[j];
#pragma unroll 8
    for (int i = 0; i < HD; i++) o += hs[g][i] * w_head[i * OUTD + j];
    out[VEC_OUT + t * OUTD + j] = o;
    if (j < 6) out[t * 6 + j] = g_x8[t * 8 + j] - pos[t * 3 + (j % 3)];
}

// ---------------- launch ----------------
#define EDGE_SMEM (16384 + 16384 + 32768 + 4096 + 256 + 24)

extern "C" void kernel_launch(void* const* d_in, const int* in_sizes, int n_in,
                              void* d_out, int out_size) {
    const float* positions = (const float*)d_in[0];
    const float* features  = (const float*)d_in[1];
    const float* w_emb     = (const float*)d_in[2];
    const float* b_emb     = (const float*)d_in[3];
    const float* we1       = (const float*)d_in[4];
    const float* be1       = (const float*)d_in[5];
    const float* we2       = (const float*)d_in[6];
    const float* be2       = (const float*)d_in[7];
    const float* wx1       = (const float*)d_in[8];
    const float* bx1       = (const float*)d_in[9];
    const float* wx2       = (const float*)d_in[10];
    const float* wh1       = (const float*)d_in[11];
    const float* bh1       = (const float*)d_in[12];
    const float* wh2       = (const float*)d_in[13];
    const float* bh2       = (const float*)d_in[14];
    const float* w_head    = (const float*)d_in[15];
    const float* b_head    = (const float*)d_in[16];
    float* out = (float*)d_out;

    cudaFuncSetAttribute(k_edge, cudaFuncAttributeMaxDynamicSharedMemorySize,
                         EDGE_SMEM);

    k_init<<<NT / 4, 256>>>(features, w_emb, b_emb, positions, we1, be1);
    for (int l = 0; l < LL; l++) {
        k_edge<<<NT, 256, EDGE_SMEM>>>(we1, we2, be2, wx1, bx1, wx2, l);
        k_update<<<NT / 4, 256>>>(wh1, bh1, wh2, bh2, we1, be1, l, l + 1);
    }
    k_final<<<NT / 4, 256>>>(positions, w_head, b_head, out);
}

// round 7
// speedup vs baseline: 2.5741x; 1.0211x over previous
#include <cuda_runtime.h>
#include <math.h>

#define NT   768
#define HD   64
#define FD   32
#define LL   2
#define OUTD 64
#define VEC_OUT (NT * 6)
#define INV_T1 (1.0f / 767.0f)

typedef unsigned long long ull;

// ---------------- device scratch ----------------
__device__ float  g_h[NT * HD];
__device__ float  g_x8[NT * 8];       // padded x_vec rows: [0..5]=x, [6..7]=pad
__device__ float2 g_A2[NT * 32];      // (A[c], A[c+32]) pairs
__device__ float2 g_B2[NT * 32];      // (B[c], B[c+32]) pairs (incl. be1)
__device__ float  g_agg[NT * HD];
__device__ float  g_xupd[NT * 6];

// silu via tanh: x * (0.5*tanh(x/2) + 0.5) — 1 MUFU, short dep chain
__device__ __forceinline__ float silu(float x) {
    float t;
    asm("tanh.approx.f32 %0, %1;" : "=f"(t) : "f"(0.5f * x));
    return x * fmaf(0.5f, t, 0.5f);
}
__device__ __forceinline__ ull ffma2(ull a, ull b, ull c) {
    ull d; asm("fma.rn.f32x2 %0, %1, %2, %3;" : "=l"(d) : "l"(a), "l"(b), "l"(c));
    return d;
}
__device__ __forceinline__ ull dup2(float x) {
    ull d; asm("mov.b64 %0, {%1, %1};" : "=l"(d) : "f"(x)); return d;
}
__device__ __forceinline__ ull pack2(float lo, float hi) {
    ull d; asm("mov.b64 %0, {%1, %2};" : "=l"(d) : "f"(lo), "f"(hi)); return d;
}
__device__ __forceinline__ void unp(ull v, float& lo, float& hi) {
    asm("mov.b64 {%0, %1}, %2;" : "=f"(lo), "=f"(hi) : "l"(v));
}

// ---------------- init: h = feat@w_emb + b ; x ; A/B for layer 0 ----------
__global__ void k_init(const float* __restrict__ feat,
                       const float* __restrict__ w_emb,
                       const float* __restrict__ b_emb,
                       const float* __restrict__ pos,
                       const float* __restrict__ we1,
                       const float* __restrict__ be1) {
    __shared__ float fs[4][FD], hs[4][HD];
    int g = threadIdx.x >> 6, j = threadIdx.x & 63;
    int t = blockIdx.x * 4 + g;
    if (j < FD) fs[g][j] = feat[t * FD + j];
    __syncthreads();
    float acc = b_emb[j];
#pragma unroll
    for (int i = 0; i < FD; i++) acc += fs[g][i] * w_emb[i * HD + j];
    g_h[t * HD + j] = acc;
    hs[g][j] = acc;
    if (j < 8) g_x8[t * 8 + j] = (j < 6) ? pos[t * 3 + (j % 3)] : 0.0f;
    __syncthreads();
    if (j < 32) {
        const float* w = we1;                 // layer 0
        float alo = 0, ahi = 0;
        float blo = be1[j], bhi = be1[j + 32];
#pragma unroll 8
        for (int i = 0; i < HD; i++) {
            float hv = hs[g][i];
            alo += hv * w[i * HD + j];
            ahi += hv * w[i * HD + j + 32];
            blo += hv * w[(64 + i) * HD + j];
            bhi += hv * w[(64 + i) * HD + j + 32];
        }
        g_A2[t * 32 + j] = make_float2(alo, ahi);
        g_B2[t * 32 + j] = make_float2(blo, bhi);
    }
}

// ---------------- edge kernel: one block per receiver ----------------
// Half-warp split: lanes 0-15 (h=0) own edges s0..s0+15, lanes 16-31 (h=1)
// own edges s0+16..s0+31. Each lane owns 4 output channels {o,o+16,o+32,o+48},
// o = lane&15. Tile: per warp, 2 half-tiles of 8 rows x 64 ull (row = edge
// pair, entry = 2 edges packed), half-tiles skewed +2 ull for bank separation.
__global__ void __launch_bounds__(256, 2) k_edge(
    const float* __restrict__ we1, const float* __restrict__ we2,
    const float* __restrict__ be2, const float* __restrict__ wx1,
    const float* __restrict__ bx1, const float* __restrict__ wx2,
    int layer) {
    const float* we1l = we1 + layer * 130 * HD;
    const float* we2l = we2 + layer * HD * HD;
    const float* wx1l = wx1 + layer * HD * HD;
    const float* wx2l = wx2 + layer * HD * 2;
    const float* be2l = be2 + layer * HD;
    const float* bx1l = bx1 + layer * HD;

    extern __shared__ float sm[];
    float4* sW2a  = (float4*)sm;          // [32*16] ch 2i2  : (w[o],w[o+16],w[o+32],w[o+48])
    float4* sW2b  = sW2a + 512;           // ch 2i2+1
    float4* sWXa  = sW2b + 512;
    float4* sWXb  = sWXa + 512;
    ull*    tAll  = (ull*)(sWXb + 512);   // 8 warps * 1028 ull
    float*  sdAll = (float*)(tAll + 8224);// 8 warps * 264 floats
    float*  sAgg  = sdAll + 2112;         // [64]
    float*  sXu   = sAgg + 64;            // [6]

    const int r = blockIdx.x;
    const int tid = threadIdx.x;
    const int warp = tid >> 5, lane = tid & 31;
    const int o = lane & 15, h = lane >> 4;
    ull*   tb  = tAll + warp * 1028;
    ull*   tbh = tb + h * 514;            // this lane's half-tile
    float* sdb = sdAll + warp * 264;

    for (int idx = tid; idx < 512; idx += 256) {
        int i2 = idx >> 4, oo = idx & 15;
        const float* w2r0 = we2l + (2 * i2) * HD;
        const float* w2r1 = w2r0 + HD;
        sW2a[idx] = make_float4(w2r0[oo], w2r0[oo + 16], w2r0[oo + 32], w2r0[oo + 48]);
        sW2b[idx] = make_float4(w2r1[oo], w2r1[oo + 16], w2r1[oo + 32], w2r1[oo + 48]);
        const float* wxr0 = wx1l + (2 * i2) * HD;
        const float* wxr1 = wxr0 + HD;
        sWXa[idx] = make_float4(wxr0[oo], wxr0[oo + 16], wxr0[oo + 32], wxr0[oo + 48]);
        sWXb[idx] = make_float4(wxr1[oo], wxr1[oo + 16], wxr1[oo + 32], wxr1[oo + 48]);
    }
    if (tid < 64) sAgg[tid] = 0.0f;
    if (tid < 6) sXu[tid] = 0.0f;
    __syncthreads();

    // hoisted per-lane constants
    const float2 Cr = g_B2[r * 32 + lane];
    const float wq00 = we1l[128 * HD + lane], wq01 = we1l[128 * HD + lane + 32];
    const float wq10 = we1l[129 * HD + lane], wq11 = we1l[129 * HD + lane + 32];
    float wx2c0[4], wx2c1[4];
#pragma unroll
    for (int c = 0; c < 4; c++) {
        wx2c0[c] = wx2l[(o + 16 * c) * 2];
        wx2c1[c] = wx2l[(o + 16 * c) * 2 + 1];
    }

    float agg[4] = {0, 0, 0, 0};
    float xacc[6] = {0, 0, 0, 0, 0, 0};

    for (int pass = 0; pass < 3; pass++) {
        const int s0 = pass * 256 + warp * 32;

        // ---- prologue: lane handles edge 'lane' of the 32-edge tile ----
        {
            const float4 xra = *(const float4*)&g_x8[r * 8];
            const float4 xrb = *(const float4*)&g_x8[r * 8 + 4];
            int s = s0 + lane;
            const float4* xp = (const float4*)&g_x8[s * 8];
            float4 xa = __ldg(xp), xb = __ldg(xp + 1);
            float d0 = xa.x - xra.x, d1 = xa.y - xra.y, d2 = xa.z - xra.z;
            float d3 = xa.w - xra.w, d4 = xb.x - xrb.x, d5 = xb.y - xrb.y;
            float sq0 = d0 * d0 + d1 * d1 + d2 * d2;
            float sq1 = d3 * d3 + d4 * d4 + d5 * d5;
            float r0 = __fdividef(1.0f, __fsqrt_rn(sq0 + 1e-8f) + 1.0f);
            float r1 = __fdividef(1.0f, __fsqrt_rn(sq1 + 1e-8f) + 1.0f);
            int sbase = lane * 8 + (h ? 4 : 0);
            *(float4*)&sdb[sbase]     = make_float4(d0 * r0, d1 * r0, d2 * r0, d3 * r1);
            *(float4*)&sdb[sbase + 4] = make_float4(d4 * r1, d5 * r1, sq0, sq1);
        }
        __syncwarp();

        // ---- t fill: all lanes fill both half-tiles, lane owns ch (lane, lane+32)
#pragma unroll 4
        for (int pp = 0; pp < 16; pp++) {
            int srow = (pp >> 3) * 514 + (pp & 7) * 64;
            int sdo = 16 * pp + ((pp >= 8) ? 4 : 0);
            float2 qqA = *(const float2*)&sdb[sdo + 6];
            float2 qqB = *(const float2*)&sdb[sdo + 14];
            float2 aA = __ldg(&g_A2[(s0 + 2 * pp) * 32 + lane]);
            float2 aB = __ldg(&g_A2[(s0 + 2 * pp + 1) * 32 + lane]);
            float pA0 = aA.x + Cr.x + qqA.x * wq00 + qqA.y * wq10;
            float pA1 = aA.y + Cr.y + qqA.x * wq01 + qqA.y * wq11;
            float pB0 = aB.x + Cr.x + qqB.x * wq00 + qqB.y * wq10;
            float pB1 = aB.y + Cr.y + qqB.x * wq01 + qqB.y * wq11;
            tb[srow + lane]      = pack2(silu(pA0), silu(pB0));
            tb[srow + lane + 32] = pack2(silu(pA1), silu(pB1));
        }
        __syncwarp();

        // ---- matmul 1: m_pre = t @ we2 + be2 ----
        ull acc[8][4];
#pragma unroll
        for (int c = 0; c < 4; c++) {
            ull b = dup2(__ldg(&be2l[o + 16 * c]));
#pragma unroll
            for (int p = 0; p < 8; p++) acc[p][c] = b;
        }
#pragma unroll 4
        for (int i2 = 0; i2 < 32; i2++) {
            float4 wa = sW2a[i2 * 16 + o];
            float4 wb = sW2b[i2 * 16 + o];
            ull da0 = dup2(wa.x), da1 = dup2(wa.y), da2 = dup2(wa.z), da3 = dup2(wa.w);
            ull db0 = dup2(wb.x), db1 = dup2(wb.y), db2 = dup2(wb.z), db3 = dup2(wb.w);
            const ulonglong2* tp = (const ulonglong2*)(tbh + 2 * i2);
#pragma unroll
            for (int p = 0; p < 8; p++) {
                ulonglong2 a = tp[p * 32];
                acc[p][0] = ffma2(a.x, da0, acc[p][0]);
                acc[p][1] = ffma2(a.x, da1, acc[p][1]);
                acc[p][2] = ffma2(a.x, da2, acc[p][2]);
                acc[p][3] = ffma2(a.x, da3, acc[p][3]);
                acc[p][0] = ffma2(a.y, db0, acc[p][0]);
                acc[p][1] = ffma2(a.y, db1, acc[p][1]);
                acc[p][2] = ffma2(a.y, db2, acc[p][2]);
                acc[p][3] = ffma2(a.y, db3, acc[p][3]);
            }
        }
        __syncwarp();   // all tile reads done before overwrite

        // ---- m = silu(m_pre) * mask ; agg ; store m into own half-tile ----
#pragma unroll
        for (int p = 0; p < 8; p++) {
            int sA = s0 + h * 16 + 2 * p;
            float k0 = (sA != r) ? 1.0f : 0.0f;
            float k1 = (sA + 1 != r) ? 1.0f : 0.0f;
#pragma unroll
            for (int c = 0; c < 4; c++) {
                float m0, m1;
                unp(acc[p][c], m0, m1);
                m0 = silu(m0) * k0;
                m1 = silu(m1) * k1;
                agg[c] += m0 + m1;
                tbh[p * 64 + o + 16 * c] = pack2(m0, m1);
            }
        }
        __syncwarp();

        // ---- matmul 2: p_pre = m @ wx1 + bx1 ----
#pragma unroll
        for (int c = 0; c < 4; c++) {
            ull b = dup2(__ldg(&bx1l[o + 16 * c]));
#pragma unroll
            for (int p = 0; p < 8; p++) acc[p][c] = b;
        }
#pragma unroll 4
        for (int i2 = 0; i2 < 32; i2++) {
            float4 wa = sWXa[i2 * 16 + o];
            float4 wb = sWXb[i2 * 16 + o];
            ull da0 = dup2(wa.x), da1 = dup2(wa.y), da2 = dup2(wa.z), da3 = dup2(wa.w);
            ull db0 = dup2(wb.x), db1 = dup2(wb.y), db2 = dup2(wb.z), db3 = dup2(wb.w);
            const ulonglong2* tp = (const ulonglong2*)(tbh + 2 * i2);
#pragma unroll
            for (int p = 0; p < 8; p++) {
                ulonglong2 a = tp[p * 32];
                acc[p][0] = ffma2(a.x, da0, acc[p][0]);
                acc[p][1] = ffma2(a.x, da1, acc[p][1]);
                acc[p][2] = ffma2(a.x, da2, acc[p][2]);
                acc[p][3] = ffma2(a.x, da3, acc[p][3]);
                acc[p][0] = ffma2(a.y, db0, acc[p][0]);
                acc[p][1] = ffma2(a.y, db1, acc[p][1]);
                acc[p][2] = ffma2(a.y, db2, acc[p][2]);
                acc[p][3] = ffma2(a.y, db3, acc[p][3]);
            }
        }

        // ---- epilogue: q = silu(p); lane-partial phi x sd (own half edges)
#pragma unroll
        for (int p = 0; p < 8; p++) {
            int e0 = h * 16 + 2 * p;
            int sdo = e0 * 8 + (h ? 4 : 0);
            float ph00 = 0, ph01 = 0, ph10 = 0, ph11 = 0;
#pragma unroll
            for (int c = 0; c < 4; c++) {
                float v0, v1;
                unp(acc[p][c], v0, v1);
                float q0 = silu(v0), q1 = silu(v1);
                ph00 += q0 * wx2c0[c]; ph01 += q0 * wx2c1[c];
                ph10 += q1 * wx2c0[c]; ph11 += q1 * wx2c1[c];
            }
            float4 s0v = *(const float4*)&sdb[sdo];
            float4 s1v = *(const float4*)&sdb[sdo + 4];
            xacc[0] += ph00 * s0v.x; xacc[1] += ph00 * s0v.y; xacc[2] += ph00 * s0v.z;
            xacc[3] += ph01 * s0v.w; xacc[4] += ph01 * s1v.x; xacc[5] += ph01 * s1v.y;
            float4 s2v = *(const float4*)&sdb[sdo + 8];
            float4 s3v = *(const float4*)&sdb[sdo + 12];
            xacc[0] += ph10 * s2v.x; xacc[1] += ph10 * s2v.y; xacc[2] += ph10 * s2v.z;
            xacc[3] += ph11 * s2v.w; xacc[4] += ph11 * s3v.x; xacc[5] += ph11 * s3v.y;
        }
        __syncwarp();   // protect sdb & tile before next pass
    }

    // ---- reductions ----
#pragma unroll
    for (int off = 16; off > 0; off >>= 1) {
#pragma unroll
        for (int c = 0; c < 6; c++)
            xacc[c] += __shfl_xor_sync(0xffffffffu, xacc[c], off);
    }
    if (lane == 0) {
#pragma unroll
        for (int c = 0; c < 6; c++) atomicAdd(&sXu[c], xacc[c]);
    }
#pragma unroll
    for (int c = 0; c < 4; c++) atomicAdd(&sAgg[o + 16 * c], agg[c]);
    __syncthreads();
    if (tid < 64) g_agg[r * HD + tid] = sAgg[tid];
    if (tid < 6) g_xupd[r * 6 + tid] = sXu[tid];
}

// ---------------- node update (+ fused A/B precompute for next layer) ----
__global__ void k_update(const float* __restrict__ wh1,
                         const float* __restrict__ bh1,
                         const float* __restrict__ wh2,
                         const float* __restrict__ bh2,
                         const float* __restrict__ we1,
                         const float* __restrict__ be1,
                         int layer, int next_layer) {
    __shared__ float hs[4][HD], as[4][HD], us[4][HD];
    int g = threadIdx.x >> 6, j = threadIdx.x & 63;
    int t = blockIdx.x * 4 + g;
    const float* w1 = wh1 + layer * 128 * HD;
    const float* w2 = wh2 + layer * HD * HD;
    hs[g][j] = g_h[t * HD + j];
    as[g][j] = g_agg[t * HD + j];
    __syncthreads();
    float u = bh1[layer * HD + j];
#pragma unroll 8
    for (int i = 0; i < HD; i++) u += hs[g][i] * w1[i * HD + j];
#pragma unroll 8
    for (int i = 0; i < HD; i++) u += as[g][i] * w1[(64 + i) * HD + j];
    us[g][j] = silu(u);
    __syncthreads();
    float o = bh2[layer * HD + j];
#pragma unroll 8
    for (int i = 0; i < HD; i++) o += us[g][i] * w2[i * HD + j];
    float hn = hs[g][j] + o;
    g_h[t * HD + j] = hn;
    if (j < 6) g_x8[t * 8 + j] += g_xupd[t * 6 + j] * INV_T1;
    if (next_layer < LL) {
        hs[g][j] = hn;          // own element only -> safe before barrier
        __syncthreads();
        const float* w = we1 + next_layer * 130 * HD;
        if (j < 32) {
            float alo = 0, ahi = 0;
            float blo = be1[next_layer * HD + j], bhi = be1[next_layer * HD + j + 32];
#pragma unroll 8
            for (int i = 0; i < HD; i++) {
                float hv = hs[g][i];
                alo += hv * w[i * HD + j];
                ahi += hv * w[i * HD + j + 32];
                blo += hv * w[(64 + i) * HD + j];
                bhi += hv * w[(64 + i) * HD + j + 32];
            }
            g_A2[t * 32 + j] = make_float2(alo, ahi);
            g_B2[t * 32 + j] = make_float2(blo, bhi);
        }
    }
}

// ---------------- final head ----------------
__global__ void k_final(const float* __restrict__ pos,
                        const float* __restrict__ w_head,
                        const float* __restrict__ b_head,
                        float* __restrict__ out) {
    __shared__ float hs[4][HD];
    int g = threadIdx.x >> 6, j = threadIdx.x & 63;
    int t = blockIdx.x * 4 + g;
    hs[g][j] = g_h[t * HD + j];
    __syncthreads();
    float o = b_head[j];
#pragma unroll 8
    for (int i = 0; i < HD; i++) o += hs[g][i] * w_head[i * OUTD + j];
    out[VEC_OUT + t * OUTD + j] = o;
    if (j < 6) out[t * 6 + j] = g_x8[t * 8 + j] - pos[t * 3 + (j % 3)];
}

// ---------------- launch ----------------
// weights 32768 + tiles 8*1028*8=65792 + sd 8*264*4=8448 + agg 256 + xu 24
#define EDGE_SMEM 107296

extern "C" void kernel_launch(void* const* d_in, const int* in_sizes, int n_in,
                              void* d_out, int out_size) {
    const float* positions = (const float*)d_in[0];
    const float* features  = (const float*)d_in[1];
    const float* w_emb     = (const float*)d_in[2];
    const float* b_emb     = (const float*)d_in[3];
    const float* we1       = (const float*)d_in[4];
    const float* be1       = (const float*)d_in[5];
    const float* we2       = (const float*)d_in[6];
    const float* be2       = (const float*)d_in[7];
    const float* wx1       = (const float*)d_in[8];
    const float* bx1       = (const float*)d_in[9];
    const float* wx2       = (const float*)d_in[10];
    const float* wh1       = (const float*)d_in[11];
    const float* bh1       = (const float*)d_in[12];
    const float* wh2       = (const float*)d_in[13];
    const float* bh2       = (const float*)d_in[14];
    const float* w_head    = (const float*)d_in[15];
    const float* b_head    = (const float*)d_in[16];
    float* out = (float*)d_out;

    cudaFuncSetAttribute(k_edge, cudaFuncAttributeMaxDynamicSharedMemorySize,
                         EDGE_SMEM);

    k_init<<<NT / 4, 256>>>(features, w_emb, b_emb, positions, we1, be1);
    for (int l = 0; l < LL; l++) {
        k_edge<<<NT, 256, EDGE_SMEM>>>(we1, we2, be2, wx1, bx1, wx2, l);
        k_update<<<NT / 4, 256>>>(wh1, bh1, wh2, bh2, we1, be1, l, l + 1);
    }
    k_final<<<NT / 4, 256>>>(positions, w_head, b_head, out);
}

// round 9
// speedup vs baseline: 4.2063x; 1.6341x over previous
#include <cuda_runtime.h>
#include <cuda_bf16.h>
#include <math.h>
#include <stdint.h>

#define NT   768
#define HD   64
#define FD   32
#define LL   2
#define OUTD 64
#define VEC_OUT (NT * 6)
#define INV_T1 (1.0f / 767.0f)

typedef unsigned long long ull;

// ---------------- device scratch ----------------
__device__ float  g_h[NT * HD];
__device__ float  g_x8[NT * 8];
__device__ float2 g_A2[NT * 32];
__device__ float2 g_B2[NT * 32];
__device__ float  g_agg[NT * HD];
__device__ float  g_xupd[NT * 6];

__device__ __forceinline__ float silu(float x) {
    float t;
    asm("tanh.approx.f32 %0, %1;" : "=f"(t) : "f"(0.5f * x));
    return x * fmaf(0.5f, t, 0.5f);
}
__device__ __forceinline__ uint32_t smem_u32(const void* p) {
    uint32_t a;
    asm("{ .reg .u64 t; cvta.to.shared.u64 t, %1; cvt.u32.u64 %0, t; }"
        : "=r"(a) : "l"(p));
    return a;
}
__device__ __forceinline__ uint32_t sw128(uint32_t off) {
    return off ^ ((off >> 3) & 0x70);
}

#define LDSM4(r, a) \
    asm volatile("ldmatrix.sync.aligned.m8n8.x4.shared.b16 {%0,%1,%2,%3}, [%4];" \
        : "=r"((r)[0]), "=r"((r)[1]), "=r"((r)[2]), "=r"((r)[3]) : "r"(a))

#define MMA16(d, a, b0, b1) \
    asm volatile("mma.sync.aligned.m16n8k16.row.col.f32.bf16.bf16.f32 " \
        "{%0,%1,%2,%3},{%4,%5,%6,%7},{%8,%9},{%0,%1,%2,%3};" \
        : "+f"((d)[0]), "+f"((d)[1]), "+f"((d)[2]), "+f"((d)[3]) \
        : "r"((a)[0]), "r"((a)[1]), "r"((a)[2]), "r"((a)[3]), "r"(b0), "r"(b1))

// split fp32[64] row into bf16 hi/lo rows, store SW128-swizzled
__device__ __forceinline__ void store_row_hilo(char* hiB, char* loB, int e,
                                               const float* t) {
#pragma unroll
    for (int j = 0; j < 8; j++) {
        uint32_t hp[4], lp[4];
#pragma unroll
        for (int q = 0; q < 4; q++) {
            float t0 = t[8 * j + 2 * q], t1 = t[8 * j + 2 * q + 1];
            uint32_t hi;
            asm("cvt.rn.satfinite.bf16x2.f32 %0, %1, %2;" : "=r"(hi) : "f"(t1), "f"(t0));
            float f0 = t0 - __uint_as_float(hi << 16);
            float f1 = t1 - __uint_as_float(hi & 0xffff0000u);
            uint32_t lo;
            asm("cvt.rn.satfinite.bf16x2.f32 %0, %1, %2;" : "=r"(lo) : "f"(f1), "f"(f0));
            hp[q] = hi; lp[q] = lo;
        }
        uint32_t sw = sw128((uint32_t)(e * 128 + j * 16));
        *(uint4*)(hiB + sw) = make_uint4(hp[0], hp[1], hp[2], hp[3]);
        *(uint4*)(loB + sw) = make_uint4(lp[0], lp[1], lp[2], lp[3]);
    }
}

// ---------------- smem layout ----------------
#define S_AHI 0
#define S_ALO 16384
#define S_W2H 32768
#define S_W2L 40960
#define S_WXH 49152
#define S_WXL 57344
#define S_AUX 65536
#define AX_WQ    0        // float4[32]
#define AX_BR    512      // float2[32]
#define AX_BE2   768      // float[64]
#define AX_BX1   1024     // float[64]
#define AX_WX2   1280     // float2[64]
#define AX_WPART 1792     // float[4*64]
#define AX_SPHI  2816     // float[128*2]
#define AX_SXU   3840     // float[6] + pad
#define EDGE_SMEM (65536 + 3872)

// 3-pass hi/lo GEMM: [128 x 64] @ [64 x 64] -> acc (this warp's 32 rows)
__device__ __forceinline__ void gemm3(uint32_t smb, uint32_t wOff, int warp,
                                      int lane, float acc[2][8][4]) {
    const int rowA = 32 * warp + (lane & 15);
    const uint32_t selA = ((uint32_t)lane >> 4) << 4;      // 0 / 16
    const uint32_t aBase = smb + S_AHI + rowA * 128;
    const uint32_t mA = (rowA & 7) << 4;
    const int rowB = (lane & 7) + ((lane & 16) >> 1);      // +8 if lane>=16
    const uint32_t selB = ((uint32_t)lane & 8) << 1;       // 0 / 16
    const uint32_t bBase = smb + wOff + rowB * 128;
    const uint32_t mB = (rowB & 7) << 4;
#pragma unroll
    for (int kt = 0; kt < 4; kt++) {
        uint32_t aAddr = aBase + ((32u * kt + selA) ^ mA);
        uint32_t ah0[4], ah1[4], al0[4], al1[4];
        LDSM4(ah0, aAddr);
        LDSM4(ah1, aAddr + 2048);
        LDSM4(al0, aAddr + 16384);
        LDSM4(al1, aAddr + 18432);
        uint32_t bx = (32u * kt + selB) ^ mB;
#pragma unroll
        for (int np = 0; np < 4; np++) {
            uint32_t bAddr = bBase + np * 2048 + bx;
            uint32_t bh[4], bl[4];
            LDSM4(bh, bAddr);
            LDSM4(bl, bAddr + 8192);
            MMA16(acc[0][2 * np], ah0, bh[0], bh[1]);
            MMA16(acc[0][2 * np], ah0, bl[0], bl[1]);
            MMA16(acc[0][2 * np], al0, bh[0], bh[1]);
            MMA16(acc[0][2 * np + 1], ah0, bh[2], bh[3]);
            MMA16(acc[0][2 * np + 1], ah0, bl[2], bl[3]);
            MMA16(acc[0][2 * np + 1], al0, bh[2], bh[3]);
            MMA16(acc[1][2 * np], ah1, bh[0], bh[1]);
            MMA16(acc[1][2 * np], ah1, bl[0], bl[1]);
            MMA16(acc[1][2 * np], al1, bh[0], bh[1]);
            MMA16(acc[1][2 * np + 1], ah1, bh[2], bh[3]);
            MMA16(acc[1][2 * np + 1], ah1, bl[2], bl[3]);
            MMA16(acc[1][2 * np + 1], al1, bh[2], bh[3]);
        }
    }
}

// ---------------- init ----------------
__global__ void k_init(const float* __restrict__ feat,
                       const float* __restrict__ w_emb,
                       const float* __restrict__ b_emb,
                       const float* __restrict__ pos,
                       const float* __restrict__ we1,
                       const float* __restrict__ be1) {
    __shared__ float fs[4][FD], hs[4][HD];
    int g = threadIdx.x >> 6, j = threadIdx.x & 63;
    int t = blockIdx.x * 4 + g;
    if (j < FD) fs[g][j] = feat[t * FD + j];
    __syncthreads();
    float acc = b_emb[j];
#pragma unroll
    for (int i = 0; i < FD; i++) acc += fs[g][i] * w_emb[i * HD + j];
    g_h[t * HD + j] = acc;
    hs[g][j] = acc;
    if (j < 8) g_x8[t * 8 + j] = (j < 6) ? pos[t * 3 + (j % 3)] : 0.0f;
    __syncthreads();
    if (j < 32) {
        const float* w = we1;
        float alo = 0, ahi = 0;
        float blo = be1[j], bhi = be1[j + 32];
#pragma unroll 8
        for (int i = 0; i < HD; i++) {
            float hv = hs[g][i];
            alo += hv * w[i * HD + j];
            ahi += hv * w[i * HD + j + 32];
            blo += hv * w[(64 + i) * HD + j];
            bhi += hv * w[(64 + i) * HD + j + 32];
        }
        g_A2[t * 32 + j] = make_float2(alo, ahi);
        g_B2[t * 32 + j] = make_float2(blo, bhi);
    }
}

// ---------------- mma.sync edge kernel: one block (128 thr) per receiver ---
__global__ void __launch_bounds__(128, 3)
k_edge_mma(const float* __restrict__ we1, const float* __restrict__ we2,
           const float* __restrict__ be2, const float* __restrict__ wx1,
           const float* __restrict__ bx1, const float* __restrict__ wx2,
           int layer) {
    const float* we1l = we1 + layer * 130 * HD;
    const float* we2l = we2 + layer * HD * HD;
    const float* wx1l = wx1 + layer * HD * HD;
    const float* wx2l = wx2 + layer * HD * 2;
    const float* be2l = be2 + layer * HD;
    const float* bx1l = bx1 + layer * HD;

    extern __shared__ char sm[];
    char* aux = sm + S_AUX;
    float4* swq  = (float4*)(aux + AX_WQ);
    float2* sbr  = (float2*)(aux + AX_BR);
    float*  sbe2 = (float*)(aux + AX_BE2);
    float*  sbx1 = (float*)(aux + AX_BX1);
    float2* swx2 = (float2*)(aux + AX_WX2);
    float*  wpart = (float*)(aux + AX_WPART);
    float*  sphi = (float*)(aux + AX_SPHI);
    float*  sxu  = (float*)(aux + AX_SXU);

    const int r = blockIdx.x;
    const int tid = threadIdx.x;
    const int warp = tid >> 5, lane = tid & 31;
    const int tig = lane & 3, gid = lane >> 2;
    const uint32_t smb = smem_u32(sm);

    // ---- preload weights as W^T[n][k] bf16 hi/lo, SW128 rows ----
    {
        int n = tid & 63, hh = tid >> 6;
        float wv[32];
#pragma unroll 8
        for (int kk = 0; kk < 32; kk++) wv[kk] = we2l[(32 * hh + kk) * 64 + n];
#pragma unroll
        for (int jj = 0; jj < 4; jj++) {
            uint32_t hp[4], lp[4];
#pragma unroll
            for (int q = 0; q < 4; q++) {
                float t0 = wv[8 * jj + 2 * q], t1 = wv[8 * jj + 2 * q + 1];
                uint32_t hi;
                asm("cvt.rn.satfinite.bf16x2.f32 %0, %1, %2;" : "=r"(hi) : "f"(t1), "f"(t0));
                float f0 = t0 - __uint_as_float(hi << 16);
                float f1 = t1 - __uint_as_float(hi & 0xffff0000u);
                uint32_t lo;
                asm("cvt.rn.satfinite.bf16x2.f32 %0, %1, %2;" : "=r"(lo) : "f"(f1), "f"(f0));
                hp[q] = hi; lp[q] = lo;
            }
            uint32_t sw = sw128((uint32_t)(n * 128 + hh * 64 + jj * 16));
            *(uint4*)(sm + S_W2H + sw) = make_uint4(hp[0], hp[1], hp[2], hp[3]);
            *(uint4*)(sm + S_W2L + sw) = make_uint4(lp[0], lp[1], lp[2], lp[3]);
        }
#pragma unroll 8
        for (int kk = 0; kk < 32; kk++) wv[kk] = wx1l[(32 * hh + kk) * 64 + n];
#pragma unroll
        for (int jj = 0; jj < 4; jj++) {
            uint32_t hp[4], lp[4];
#pragma unroll
            for (int q = 0; q < 4; q++) {
                float t0 = wv[8 * jj + 2 * q], t1 = wv[8 * jj + 2 * q + 1];
                uint32_t hi;
                asm("cvt.rn.satfinite.bf16x2.f32 %0, %1, %2;" : "=r"(hi) : "f"(t1), "f"(t0));
                float f0 = t0 - __uint_as_float(hi << 16);
                float f1 = t1 - __uint_as_float(hi & 0xffff0000u);
                uint32_t lo;
                asm("cvt.rn.satfinite.bf16x2.f32 %0, %1, %2;" : "=r"(lo) : "f"(f1), "f"(f0));
                hp[q] = hi; lp[q] = lo;
            }
            uint32_t sw = sw128((uint32_t)(n * 128 + hh * 64 + jj * 16));
            *(uint4*)(sm + S_WXH + sw) = make_uint4(hp[0], hp[1], hp[2], hp[3]);
            *(uint4*)(sm + S_WXL + sw) = make_uint4(lp[0], lp[1], lp[2], lp[3]);
        }
    }
    if (tid < 32) {
        swq[tid] = make_float4(we1l[8192 + tid], we1l[8256 + tid],
                               we1l[8192 + 32 + tid], we1l[8256 + 32 + tid]);
        sbr[tid] = g_B2[r * 32 + tid];
    }
    if (tid < 64) {
        sbe2[tid] = be2l[tid];
        sbx1[tid] = bx1l[tid];
        swx2[tid] = make_float2(wx2l[2 * tid], wx2l[2 * tid + 1]);
    }
    if (tid < 6) sxu[tid] = 0.0f;
    __syncthreads();

    const float4 xra = *(const float4*)&g_x8[r * 8];
    const float4 xrb = *(const float4*)&g_x8[r * 8 + 4];

    float aggv[16];
#pragma unroll
    for (int i = 0; i < 16; i++) aggv[i] = 0.0f;
    float xacc[6] = {0, 0, 0, 0, 0, 0};

    for (int tile = 0; tile < 6; tile++) {
        const int s0 = tile * 128;
        const int s = s0 + tid;

        // ---- edge geometry (thread owns edge row tid) ----
        float4 xa = __ldg((const float4*)&g_x8[s * 8]);
        float4 xb = __ldg((const float4*)&g_x8[s * 8 + 4]);
        float d0 = xa.x - xra.x, d1 = xa.y - xra.y, d2 = xa.z - xra.z;
        float d3 = xa.w - xra.w, d4 = xb.x - xrb.x, d5 = xb.y - xrb.y;
        float sq0 = d0 * d0 + d1 * d1 + d2 * d2;
        float sq1 = d3 * d3 + d4 * d4 + d5 * d5;
        float r0 = __fdividef(1.0f, __fsqrt_rn(sq0 + 1e-8f) + 1.0f);
        float r1 = __fdividef(1.0f, __fsqrt_rn(sq1 + 1e-8f) + 1.0f);
        float sd0 = d0 * r0, sd1 = d1 * r0, sd2 = d2 * r0;
        float sd3 = d3 * r1, sd4 = d4 * r1, sd5 = d5 * r1;

        // ---- t-fill ----
        {
            float tv[64];
            const float4* arow = (const float4*)&g_A2[s * 32];
#pragma unroll
            for (int i2 = 0; i2 < 16; i2++) {
                float4 a4 = __ldg(&arow[i2]);
                int i = 2 * i2;
                {
                    float4 wq = swq[i]; float2 br = sbr[i];
                    tv[i]      = silu(a4.x + br.x + sq0 * wq.x + sq1 * wq.y);
                    tv[i + 32] = silu(a4.y + br.y + sq0 * wq.z + sq1 * wq.w);
                }
                {
                    float4 wq = swq[i + 1]; float2 br = sbr[i + 1];
                    tv[i + 1]  = silu(a4.z + br.x + sq0 * wq.x + sq1 * wq.y);
                    tv[i + 33] = silu(a4.w + br.y + sq0 * wq.z + sq1 * wq.w);
                }
            }
            store_row_hilo(sm + S_AHI, sm + S_ALO, tid, tv);
        }
        __syncwarp();

        // ---- GEMM 1: m_pre = t @ we2 + be2 ----
        float acc[2][8][4];
        {
            int n0 = 2 * tig;
#pragma unroll
            for (int nt = 0; nt < 8; nt++) {
                float2 b = *(const float2*)&sbe2[8 * nt + n0];
                acc[0][nt][0] = b.x; acc[0][nt][1] = b.y;
                acc[0][nt][2] = b.x; acc[0][nt][3] = b.y;
                acc[1][nt][0] = b.x; acc[1][nt][1] = b.y;
                acc[1][nt][2] = b.x; acc[1][nt][3] = b.y;
            }
        }
        gemm3(smb, S_W2H, warp, lane, acc);

        // ---- epilogue 1: m = silu(.)*mask ; agg ; store m hi/lo ----
#pragma unroll
        for (int mt = 0; mt < 2; mt++) {
            int rA = 32 * warp + 16 * mt + gid;
            int rB = rA + 8;
            float vA = (s0 + rA != r) ? 1.0f : 0.0f;
            float vB = (s0 + rB != r) ? 1.0f : 0.0f;
            uint32_t offA = (uint32_t)(rA * 128) + 4 * tig;
            uint32_t offB = (uint32_t)(rB * 128) + 4 * tig;
            uint32_t mkA = (rA & 7) << 4, mkB = (rB & 7) << 4;
#pragma unroll
            for (int nt = 0; nt < 8; nt++) {
                float m0 = silu(acc[mt][nt][0]) * vA;
                float m1 = silu(acc[mt][nt][1]) * vA;
                float m2 = silu(acc[mt][nt][2]) * vB;
                float m3 = silu(acc[mt][nt][3]) * vB;
                aggv[2 * nt]     += m0 + m2;
                aggv[2 * nt + 1] += m1 + m3;
                uint32_t hiA, loA, hiB, loB;
                asm("cvt.rn.satfinite.bf16x2.f32 %0, %1, %2;" : "=r"(hiA) : "f"(m1), "f"(m0));
                asm("cvt.rn.satfinite.bf16x2.f32 %0, %1, %2;" : "=r"(hiB) : "f"(m3), "f"(m2));
                {
                    float f0 = m0 - __uint_as_float(hiA << 16);
                    float f1 = m1 - __uint_as_float(hiA & 0xffff0000u);
                    asm("cvt.rn.satfinite.bf16x2.f32 %0, %1, %2;" : "=r"(loA) : "f"(f1), "f"(f0));
                    float f2 = m2 - __uint_as_float(hiB << 16);
                    float f3 = m3 - __uint_as_float(hiB & 0xffff0000u);
                    asm("cvt.rn.satfinite.bf16x2.f32 %0, %1, %2;" : "=r"(loB) : "f"(f3), "f"(f2));
                }
                uint32_t cA = offA + (((uint32_t)(16 * nt)) ^ mkA);
                uint32_t cB = offB + (((uint32_t)(16 * nt)) ^ mkB);
                *(uint32_t*)(sm + S_AHI + cA) = hiA;
                *(uint32_t*)(sm + S_ALO + cA) = loA;
                *(uint32_t*)(sm + S_AHI + cB) = hiB;
                *(uint32_t*)(sm + S_ALO + cB) = loB;
            }
        }
        __syncwarp();

        // ---- GEMM 2: p_pre = m @ wx1 + bx1 ----
        {
            int n0 = 2 * tig;
#pragma unroll
            for (int nt = 0; nt < 8; nt++) {
                float2 b = *(const float2*)&sbx1[8 * nt + n0];
                acc[0][nt][0] = b.x; acc[0][nt][1] = b.y;
                acc[0][nt][2] = b.x; acc[0][nt][3] = b.y;
                acc[1][nt][0] = b.x; acc[1][nt][1] = b.y;
                acc[1][nt][2] = b.x; acc[1][nt][3] = b.y;
            }
        }
        gemm3(smb, S_WXH, warp, lane, acc);

        // ---- epilogue 2: q = silu(p); phi = q @ wx2 (quad-partial) ----
        {
            float ph[4][2] = {{0, 0}, {0, 0}, {0, 0}, {0, 0}};
#pragma unroll
            for (int mt = 0; mt < 2; mt++) {
#pragma unroll
                for (int nt = 0; nt < 8; nt++) {
                    int n0 = 8 * nt + 2 * tig;
                    float4 w = *(const float4*)&swx2[n0];   // (w0.x w0.y w1.x w1.y)
                    float q0 = silu(acc[mt][nt][0]);
                    float q1 = silu(acc[mt][nt][1]);
                    float q2 = silu(acc[mt][nt][2]);
                    float q3 = silu(acc[mt][nt][3]);
                    ph[2 * mt][0]     += q0 * w.x + q1 * w.z;
                    ph[2 * mt][1]     += q0 * w.y + q1 * w.w;
                    ph[2 * mt + 1][0] += q2 * w.x + q3 * w.z;
                    ph[2 * mt + 1][1] += q2 * w.y + q3 * w.w;
                }
            }
#pragma unroll
            for (int k = 0; k < 4; k++) {
#pragma unroll
                for (int c = 0; c < 2; c++) {
                    ph[k][c] += __shfl_xor_sync(0xffffffffu, ph[k][c], 1);
                    ph[k][c] += __shfl_xor_sync(0xffffffffu, ph[k][c], 2);
                }
            }
            if (tig == 0) {
#pragma unroll
                for (int k = 0; k < 4; k++) {
                    int row = 32 * warp + 16 * (k >> 1) + 8 * (k & 1) + gid;
                    sphi[row * 2] = ph[k][0];
                    sphi[row * 2 + 1] = ph[k][1];
                }
            }
        }
        __syncwarp();
        {
            float2 p = *(const float2*)&sphi[tid * 2];
            xacc[0] += p.x * sd0; xacc[1] += p.x * sd1; xacc[2] += p.x * sd2;
            xacc[3] += p.y * sd3; xacc[4] += p.y * sd4; xacc[5] += p.y * sd5;
        }
        __syncwarp();
    }

    // ---- reductions ----
#pragma unroll
    for (int i = 0; i < 16; i++) {
        aggv[i] += __shfl_xor_sync(0xffffffffu, aggv[i], 4);
        aggv[i] += __shfl_xor_sync(0xffffffffu, aggv[i], 8);
        aggv[i] += __shfl_xor_sync(0xffffffffu, aggv[i], 16);
    }
    if (lane < 4) {
#pragma unroll
        for (int nt = 0; nt < 8; nt++) {
            wpart[warp * 64 + 8 * nt + 2 * lane]     = aggv[2 * nt];
            wpart[warp * 64 + 8 * nt + 2 * lane + 1] = aggv[2 * nt + 1];
        }
    }
#pragma unroll
    for (int c = 0; c < 6; c++) {
        float v = xacc[c];
#pragma unroll
        for (int off = 16; off > 0; off >>= 1)
            v += __shfl_xor_sync(0xffffffffu, v, off);
        if (lane == 0) atomicAdd(&sxu[c], v);
    }
    __syncthreads();
    if (tid < 64)
        g_agg[r * HD + tid] = wpart[tid] + wpart[64 + tid] +
                              wpart[128 + tid] + wpart[192 + tid];
    if (tid < 6) g_xupd[r * 6 + tid] = sxu[tid];
}

// ---------------- node update (+ fused A/B precompute) ----------------
__global__ void k_update(const float* __restrict__ wh1,
                         const float* __restrict__ bh1,
                         const float* __restrict__ wh2,
                         const float* __restrict__ bh2,
                         const float* __restrict__ we1,
                         const float* __restrict__ be1,
                         int layer, int next_layer) {
    __shared__ float hs[4][HD], as[4][HD], us[4][HD];
    int g = threadIdx.x >> 6, j = threadIdx.x & 63;
    int t = blockIdx.x * 4 + g;
    const float* w1 = wh1 + layer * 128 * HD;
    const float* w2 = wh2 + layer * HD * HD;
    hs[g][j] = g_h[t * HD + j];
    as[g][j] = g_agg[t * HD + j];
    __syncthreads();
    float u = bh1[layer * HD + j];
#pragma unroll 8
    for (int i = 0; i < HD; i++) u += hs[g][i] * w1[i * HD + j];
#pragma unroll 8
    for (int i = 0; i < HD; i++) u += as[g][i] * w1[(64 + i) * HD + j];
    us[g][j] = silu(u);
    __syncthreads();
    float o = bh2[layer * HD + j];
#pragma unroll 8
    for (int i = 0; i < HD; i++) o += us[g][i] * w2[i * HD + j];
    float hn = hs[g][j] + o;
    g_h[t * HD + j] = hn;
    if (j < 6) g_x8[t * 8 + j] += g_xupd[t * 6 + j] * INV_T1;
    if (next_layer < LL) {
        hs[g][j] = hn;
        __syncthreads();
        const float* w = we1 + next_layer * 130 * HD;
        if (j < 32) {
            float alo = 0, ahi = 0;
            float blo = be1[next_layer * HD + j], bhi = be1[next_layer * HD + j + 32];
#pragma unroll 8
            for (int i = 0; i < HD; i++) {
                float hv = hs[g][i];
                alo += hv * w[i * HD + j];
                ahi += hv * w[i * HD + j + 32];
                blo += hv * w[(64 + i) * HD + j];
                bhi += hv * w[(64 + i) * HD + j + 32];
            }
            g_A2[t * 32 + j] = make_float2(alo, ahi);
            g_B2[t * 32 + j] = make_float2(blo, bhi);
        }
    }
}

// ---------------- final head ----------------
__global__ void k_final(const float* __restrict__ pos,
                        const float* __restrict__ w_head,
                        const float* __restrict__ b_head,
                        float* __restrict__ out) {
    __shared__ float hs[4][HD];
    int g = threadIdx.x >> 6, j = threadIdx.x & 63;
    int t = blockIdx.x * 4 + g;
    hs[g][j] = g_h[t * HD + j];
    __syncthreads();
    float o = b_head[j];
#pragma unroll 8
    for (int i = 0; i < HD; i++) o += hs[g][i] * w_head[i * OUTD + j];
    out[VEC_OUT + t * OUTD + j] = o;
    if (j < 6) out[t * 6 + j] = g_x8[t * 8 + j] - pos[t * 3 + (j % 3)];
}

// ---------------- launch ----------------
extern "C" void kernel_launch(void* const* d_in, const int* in_sizes, int n_in,
                              void* d_out, int out_size) {
    const float* positions = (const float*)d_in[0];
    const float* features  = (const float*)d_in[1];
    const float* w_emb     = (const float*)d_in[2];
    const float* b_emb     = (const float*)d_in[3];
    const float* we1       = (const float*)d_in[4];
    const float* be1       = (const float*)d_in[5];
    const float* we2       = (const float*)d_in[6];
    const float* be2       = (const float*)d_in[7];
    const float* wx1       = (const float*)d_in[8];
    const float* bx1       = (const float*)d_in[9];
    const float* wx2       = (const float*)d_in[10];
    const float* wh1       = (const float*)d_in[11];
    const float* bh1       = (const float*)d_in[12];
    const float* wh2       = (const float*)d_in[13];
    const float* bh2       = (const float*)d_in[14];
    const float* w_head    = (const float*)d_in[15];
    const float* b_head    = (const float*)d_in[16];
    float* out = (float*)d_out;

    cudaFuncSetAttribute(k_edge_mma, cudaFuncAttributeMaxDynamicSharedMemorySize,
                         EDGE_SMEM);

    k_init<<<NT / 4, 256>>>(features, w_emb, b_emb, positions, we1, be1);
    for (int l = 0; l < LL; l++) {
        k_edge_mma<<<NT, 128, EDGE_SMEM>>>(we1, we2, be2, wx1, bx1, wx2, l);
        k_update<<<NT / 4, 256>>>(wh1, bh1, wh2, bh2, we1, be1, l, l + 1);
    }
    k_final<<<NT / 4, 256>>>(positions, w_head, b_head, out);
}

// round 10
// speedup vs baseline: 4.3463x; 1.0333x over previous
#include <cuda_runtime.h>
#include <cuda_bf16.h>
#include <math.h>
#include <stdint.h>

#define NT   768
#define HD   64
#define FD   32
#define LL   2
#define OUTD 64
#define VEC_OUT (NT * 6)
#define INV_T1 (1.0f / 767.0f)

typedef unsigned long long ull;

// ---------------- device scratch ----------------
__device__ float  g_h[NT * HD];
__device__ float  g_x8[NT * 8];
__device__ float2 g_A2[NT * 32];
__device__ float2 g_B2[NT * 32];
__device__ float  g_agg[NT * HD];
__device__ float  g_xupd[NT * 6];

__device__ __forceinline__ float silu(float x) {
    float t;
    asm("tanh.approx.f32 %0, %1;" : "=f"(t) : "f"(0.5f * x));
    return x * fmaf(0.5f, t, 0.5f);
}
__device__ __forceinline__ uint32_t smem_u32(const void* p) {
    uint32_t a;
    asm("{ .reg .u64 t; cvta.to.shared.u64 t, %1; cvt.u32.u64 %0, t; }"
        : "=r"(a) : "l"(p));
    return a;
}
__device__ __forceinline__ uint32_t sw128(uint32_t off) {
    return off ^ ((off >> 3) & 0x70);
}

#define LDSM4(r, a) \
    asm volatile("ldmatrix.sync.aligned.m8n8.x4.shared.b16 {%0,%1,%2,%3}, [%4];" \
        : "=r"((r)[0]), "=r"((r)[1]), "=r"((r)[2]), "=r"((r)[3]) : "r"(a))

#define MMA16(d, a, b0, b1) \
    asm volatile("mma.sync.aligned.m16n8k16.row.col.f32.bf16.bf16.f32 " \
        "{%0,%1,%2,%3},{%4,%5,%6,%7},{%8,%9},{%0,%1,%2,%3};" \
        : "+f"((d)[0]), "+f"((d)[1]), "+f"((d)[2]), "+f"((d)[3]) \
        : "r"((a)[0]), "r"((a)[1]), "r"((a)[2]), "r"((a)[3]), "r"(b0), "r"(b1))

// split fp32[64] row into bf16 hi/lo rows, store SW128-swizzled
__device__ __forceinline__ void store_row_hilo(char* hiB, char* loB, int e,
                                               const float* t) {
#pragma unroll
    for (int j = 0; j < 8; j++) {
        uint32_t hp[4], lp[4];
#pragma unroll
        for (int q = 0; q < 4; q++) {
            float t0 = t[8 * j + 2 * q], t1 = t[8 * j + 2 * q + 1];
            uint32_t hi;
            asm("cvt.rn.satfinite.bf16x2.f32 %0, %1, %2;" : "=r"(hi) : "f"(t1), "f"(t0));
            float f0 = t0 - __uint_as_float(hi << 16);
            float f1 = t1 - __uint_as_float(hi & 0xffff0000u);
            uint32_t lo;
            asm("cvt.rn.satfinite.bf16x2.f32 %0, %1, %2;" : "=r"(lo) : "f"(f1), "f"(f0));
            hp[q] = hi; lp[q] = lo;
        }
        uint32_t sw = sw128((uint32_t)(e * 128 + j * 16));
        *(uint4*)(hiB + sw) = make_uint4(hp[0], hp[1], hp[2], hp[3]);
        *(uint4*)(loB + sw) = make_uint4(lp[0], lp[1], lp[2], lp[3]);
    }
}

// ---------------- smem layout ----------------
#define S_AHI 0
#define S_ALO 16384
#define S_W2H 32768
#define S_W2L 40960
#define S_WXH 49152
#define S_WXL 57344
#define S_AUX 65536
#define AX_WQ    0        // float4[32]
#define AX_BR    512      // float2[32]
#define AX_BE2   768      // float[64]
#define AX_BX1   1024     // float[64]
#define AX_WX2   1280     // float2[64]
#define AX_WPART 1792     // float[4*64]
#define AX_SPHI  2816     // float[128*2]
#define AX_SXU   3840     // float[6] + pad
#define EDGE_SMEM (65536 + 3872)

// GEMM1: 3-pass hi/lo, A from smem tiles: [128 x 64] @ [64 x 64]
__device__ __forceinline__ void gemm_smemA(uint32_t smb, uint32_t wOff, int warp,
                                           int lane, float acc[2][8][4]) {
    const int rowA = 32 * warp + (lane & 15);
    const uint32_t selA = ((uint32_t)lane >> 4) << 4;
    const uint32_t aBase = smb + S_AHI + rowA * 128;
    const uint32_t mA = (rowA & 7) << 4;
    const int rowB = (lane & 7) + ((lane & 16) >> 1);
    const uint32_t selB = ((uint32_t)lane & 8) << 1;
    const uint32_t bBase = smb + wOff + rowB * 128;
    const uint32_t mB = (rowB & 7) << 4;
#pragma unroll
    for (int kt = 0; kt < 4; kt++) {
        uint32_t aAddr = aBase + ((32u * kt + selA) ^ mA);
        uint32_t ah0[4], ah1[4], al0[4], al1[4];
        LDSM4(ah0, aAddr);
        LDSM4(ah1, aAddr + 2048);
        LDSM4(al0, aAddr + 16384);
        LDSM4(al1, aAddr + 18432);
        uint32_t bx = (32u * kt + selB) ^ mB;
#pragma unroll
        for (int np = 0; np < 4; np++) {
            uint32_t bAddr = bBase + np * 2048 + bx;
            uint32_t bh[4], bl[4];
            LDSM4(bh, bAddr);
            LDSM4(bl, bAddr + 8192);
            MMA16(acc[0][2 * np], ah0, bh[0], bh[1]);
            MMA16(acc[0][2 * np], ah0, bl[0], bl[1]);
            MMA16(acc[0][2 * np], al0, bh[0], bh[1]);
            MMA16(acc[0][2 * np + 1], ah0, bh[2], bh[3]);
            MMA16(acc[0][2 * np + 1], ah0, bl[2], bl[3]);
            MMA16(acc[0][2 * np + 1], al0, bh[2], bh[3]);
            MMA16(acc[1][2 * np], ah1, bh[0], bh[1]);
            MMA16(acc[1][2 * np], ah1, bl[0], bl[1]);
            MMA16(acc[1][2 * np], al1, bh[0], bh[1]);
            MMA16(acc[1][2 * np + 1], ah1, bh[2], bh[3]);
            MMA16(acc[1][2 * np + 1], ah1, bl[2], bl[3]);
            MMA16(acc[1][2 * np + 1], al1, bh[2], bh[3]);
        }
    }
}

// GEMM2: 3-pass hi/lo, A fragments live in registers (mhi/mlo)
__device__ __forceinline__ void gemm_regA(uint32_t smb, uint32_t wOff, int lane,
                                          const uint32_t mhi[2][16],
                                          const uint32_t mlo[2][16],
                                          float acc[2][8][4]) {
    const int rowB = (lane & 7) + ((lane & 16) >> 1);
    const uint32_t selB = ((uint32_t)lane & 8) << 1;
    const uint32_t bBase = smb + wOff + rowB * 128;
    const uint32_t mB = (rowB & 7) << 4;
#pragma unroll
    for (int kt = 0; kt < 4; kt++) {
        uint32_t bx = (32u * kt + selB) ^ mB;
#pragma unroll
        for (int np = 0; np < 4; np++) {
            uint32_t bAddr = bBase + np * 2048 + bx;
            uint32_t bh[4], bl[4];
            LDSM4(bh, bAddr);
            LDSM4(bl, bAddr + 8192);
#pragma unroll
            for (int mt = 0; mt < 2; mt++) {
                const uint32_t* ah = &mhi[mt][4 * kt];
                const uint32_t* al = &mlo[mt][4 * kt];
                MMA16(acc[mt][2 * np], ah, bh[0], bh[1]);
                MMA16(acc[mt][2 * np], ah, bl[0], bl[1]);
                MMA16(acc[mt][2 * np], al, bh[0], bh[1]);
                MMA16(acc[mt][2 * np + 1], ah, bh[2], bh[3]);
                MMA16(acc[mt][2 * np + 1], ah, bl[2], bl[3]);
                MMA16(acc[mt][2 * np + 1], al, bh[2], bh[3]);
            }
        }
    }
}

// ---------------- init ----------------
__global__ void k_init(const float* __restrict__ feat,
                       const float* __restrict__ w_emb,
                       const float* __restrict__ b_emb,
                       const float* __restrict__ pos,
                       const float* __restrict__ we1,
                       const float* __restrict__ be1) {
    __shared__ float fs[4][FD], hs[4][HD];
    int g = threadIdx.x >> 6, j = threadIdx.x & 63;
    int t = blockIdx.x * 4 + g;
    if (j < FD) fs[g][j] = feat[t * FD + j];
    __syncthreads();
    float acc = b_emb[j];
#pragma unroll
    for (int i = 0; i < FD; i++) acc += fs[g][i] * w_emb[i * HD + j];
    g_h[t * HD + j] = acc;
    hs[g][j] = acc;
    if (j < 8) g_x8[t * 8 + j] = (j < 6) ? pos[t * 3 + (j % 3)] : 0.0f;
    __syncthreads();
    if (j < 32) {
        const float* w = we1;
        float alo = 0, ahi = 0;
        float blo = be1[j], bhi = be1[j + 32];
#pragma unroll 8
        for (int i = 0; i < HD; i++) {
            float hv = hs[g][i];
            alo += hv * w[i * HD + j];
            ahi += hv * w[i * HD + j + 32];
            blo += hv * w[(64 + i) * HD + j];
            bhi += hv * w[(64 + i) * HD + j + 32];
        }
        g_A2[t * 32 + j] = make_float2(alo, ahi);
        g_B2[t * 32 + j] = make_float2(blo, bhi);
    }
}

// ---------------- mma.sync edge kernel: one block (128 thr) per receiver ---
__global__ void __launch_bounds__(128, 3)
k_edge_mma(const float* __restrict__ we1, const float* __restrict__ we2,
           const float* __restrict__ be2, const float* __restrict__ wx1,
           const float* __restrict__ bx1, const float* __restrict__ wx2,
           int layer) {
    const float* we1l = we1 + layer * 130 * HD;
    const float* we2l = we2 + layer * HD * HD;
    const float* wx1l = wx1 + layer * HD * HD;
    const float* wx2l = wx2 + layer * HD * 2;
    const float* be2l = be2 + layer * HD;
    const float* bx1l = bx1 + layer * HD;

    extern __shared__ char sm[];
    char* aux = sm + S_AUX;
    float4* swq  = (float4*)(aux + AX_WQ);
    float2* sbr  = (float2*)(aux + AX_BR);
    float*  sbe2 = (float*)(aux + AX_BE2);
    float*  sbx1 = (float*)(aux + AX_BX1);
    float2* swx2 = (float2*)(aux + AX_WX2);
    float*  wpart = (float*)(aux + AX_WPART);
    float*  sphi = (float*)(aux + AX_SPHI);
    float*  sxu  = (float*)(aux + AX_SXU);

    const int r = blockIdx.x;
    const int tid = threadIdx.x;
    const int warp = tid >> 5, lane = tid & 31;
    const int tig = lane & 3, gid = lane >> 2;
    const uint32_t smb = smem_u32(sm);

    // ---- preload weights as W^T[n][k] bf16 hi/lo, SW128 rows ----
    {
        int n = tid & 63, hh = tid >> 6;
        float wv[32];
#pragma unroll 8
        for (int kk = 0; kk < 32; kk++) wv[kk] = we2l[(32 * hh + kk) * 64 + n];
#pragma unroll
        for (int jj = 0; jj < 4; jj++) {
            uint32_t hp[4], lp[4];
#pragma unroll
            for (int q = 0; q < 4; q++) {
                float t0 = wv[8 * jj + 2 * q], t1 = wv[8 * jj + 2 * q + 1];
                uint32_t hi;
                asm("cvt.rn.satfinite.bf16x2.f32 %0, %1, %2;" : "=r"(hi) : "f"(t1), "f"(t0));
                float f0 = t0 - __uint_as_float(hi << 16);
                float f1 = t1 - __uint_as_float(hi & 0xffff0000u);
                uint32_t lo;
                asm("cvt.rn.satfinite.bf16x2.f32 %0, %1, %2;" : "=r"(lo) : "f"(f1), "f"(f0));
                hp[q] = hi; lp[q] = lo;
            }
            uint32_t sw = sw128((uint32_t)(n * 128 + hh * 64 + jj * 16));
            *(uint4*)(sm + S_W2H + sw) = make_uint4(hp[0], hp[1], hp[2], hp[3]);
            *(uint4*)(sm + S_W2L + sw) = make_uint4(lp[0], lp[1], lp[2], lp[3]);
        }
#pragma unroll 8
        for (int kk = 0; kk < 32; kk++) wv[kk] = wx1l[(32 * hh + kk) * 64 + n];
#pragma unroll
        for (int jj = 0; jj < 4; jj++) {
            uint32_t hp[4], lp[4];
#pragma unroll
            for (int q = 0; q < 4; q++) {
                float t0 = wv[8 * jj + 2 * q], t1 = wv[8 * jj + 2 * q + 1];
                uint32_t hi;
                asm("cvt.rn.satfinite.bf16x2.f32 %0, %1, %2;" : "=r"(hi) : "f"(t1), "f"(t0));
                float f0 = t0 - __uint_as_float(hi << 16);
                float f1 = t1 - __uint_as_float(hi & 0xffff0000u);
                uint32_t lo;
                asm("cvt.rn.satfinite.bf16x2.f32 %0, %1, %2;" : "=r"(lo) : "f"(f1), "f"(f0));
                hp[q] = hi; lp[q] = lo;
            }
            uint32_t sw = sw128((uint32_t)(n * 128 + hh * 64 + jj * 16));
            *(uint4*)(sm + S_WXH + sw) = make_uint4(hp[0], hp[1], hp[2], hp[3]);
            *(uint4*)(sm + S_WXL + sw) = make_uint4(lp[0], lp[1], lp[2], lp[3]);
        }
    }
    if (tid < 32) {
        swq[tid] = make_float4(we1l[8192 + tid], we1l[8256 + tid],
                               we1l[8192 + 32 + tid], we1l[8256 + 32 + tid]);
        sbr[tid] = g_B2[r * 32 + tid];
    }
    if (tid < 64) {
        sbe2[tid] = be2l[tid];
        sbx1[tid] = bx1l[tid];
        swx2[tid] = make_float2(wx2l[2 * tid], wx2l[2 * tid + 1]);
    }
    if (tid < 6) sxu[tid] = 0.0f;
    __syncthreads();

    const float4 xra = *(const float4*)&g_x8[r * 8];
    const float4 xrb = *(const float4*)&g_x8[r * 8 + 4];

    float aggv[16];
#pragma unroll
    for (int i = 0; i < 16; i++) aggv[i] = 0.0f;
    float xacc[6] = {0, 0, 0, 0, 0, 0};

    for (int tile = 0; tile < 6; tile++) {
        const int s0 = tile * 128;
        const int s = s0 + tid;

        // ---- edge geometry (thread owns edge row tid) ----
        float4 xa = __ldg((const float4*)&g_x8[s * 8]);
        float4 xb = __ldg((const float4*)&g_x8[s * 8 + 4]);
        float d0 = xa.x - xra.x, d1 = xa.y - xra.y, d2 = xa.z - xra.z;
        float d3 = xa.w - xra.w, d4 = xb.x - xrb.x, d5 = xb.y - xrb.y;
        float sq0 = d0 * d0 + d1 * d1 + d2 * d2;
        float sq1 = d3 * d3 + d4 * d4 + d5 * d5;
        float r0 = __fdividef(1.0f, __fsqrt_rn(sq0 + 1e-8f) + 1.0f);
        float r1 = __fdividef(1.0f, __fsqrt_rn(sq1 + 1e-8f) + 1.0f);
        float sd0 = d0 * r0, sd1 = d1 * r0, sd2 = d2 * r0;
        float sd3 = d3 * r1, sd4 = d4 * r1, sd5 = d5 * r1;

        // ---- t-fill (A tile for GEMM1) ----
        {
            float tv[64];
            const float4* arow = (const float4*)&g_A2[s * 32];
#pragma unroll
            for (int i2 = 0; i2 < 16; i2++) {
                float4 a4 = __ldg(&arow[i2]);
                int i = 2 * i2;
                {
                    float4 wq = swq[i]; float2 br = sbr[i];
                    tv[i]      = silu(a4.x + br.x + sq0 * wq.x + sq1 * wq.y);
                    tv[i + 32] = silu(a4.y + br.y + sq0 * wq.z + sq1 * wq.w);
                }
                {
                    float4 wq = swq[i + 1]; float2 br = sbr[i + 1];
                    tv[i + 1]  = silu(a4.z + br.x + sq0 * wq.x + sq1 * wq.y);
                    tv[i + 33] = silu(a4.w + br.y + sq0 * wq.z + sq1 * wq.w);
                }
            }
            store_row_hilo(sm + S_AHI, sm + S_ALO, tid, tv);
        }
        __syncwarp();

        // ---- GEMM 1: m_pre = t @ we2 + be2 ----
        float acc[2][8][4];
        {
            int n0 = 2 * tig;
#pragma unroll
            for (int nt = 0; nt < 8; nt++) {
                float2 b = *(const float2*)&sbe2[8 * nt + n0];
                acc[0][nt][0] = b.x; acc[0][nt][1] = b.y;
                acc[0][nt][2] = b.x; acc[0][nt][3] = b.y;
                acc[1][nt][0] = b.x; acc[1][nt][1] = b.y;
                acc[1][nt][2] = b.x; acc[1][nt][3] = b.y;
            }
        }
        gemm_smemA(smb, S_W2H, warp, lane, acc);

        // ---- epilogue 1 (all-register): m = silu(.)*mask ; agg ;
        //      build GEMM2 A-fragments mhi/mlo directly from acc ----
        uint32_t mhi[2][16], mlo[2][16];
#pragma unroll
        for (int mt = 0; mt < 2; mt++) {
            int rA = 32 * warp + 16 * mt + gid;
            float vA = (s0 + rA != r) ? 1.0f : 0.0f;
            float vB = (s0 + rA + 8 != r) ? 1.0f : 0.0f;
#pragma unroll
            for (int nt = 0; nt < 8; nt++) {
                float m0 = silu(acc[mt][nt][0]) * vA;
                float m1 = silu(acc[mt][nt][1]) * vA;
                float m2 = silu(acc[mt][nt][2]) * vB;
                float m3 = silu(acc[mt][nt][3]) * vB;
                aggv[2 * nt]     += m0 + m2;
                aggv[2 * nt + 1] += m1 + m3;
                uint32_t h0, h1, l0, l1;
                asm("cvt.rn.satfinite.bf16x2.f32 %0, %1, %2;" : "=r"(h0) : "f"(m1), "f"(m0));
                asm("cvt.rn.satfinite.bf16x2.f32 %0, %1, %2;" : "=r"(h1) : "f"(m3), "f"(m2));
                float f0 = m0 - __uint_as_float(h0 << 16);
                float f1 = m1 - __uint_as_float(h0 & 0xffff0000u);
                float f2 = m2 - __uint_as_float(h1 << 16);
                float f3 = m3 - __uint_as_float(h1 & 0xffff0000u);
                asm("cvt.rn.satfinite.bf16x2.f32 %0, %1, %2;" : "=r"(l0) : "f"(f1), "f"(f0));
                asm("cvt.rn.satfinite.bf16x2.f32 %0, %1, %2;" : "=r"(l1) : "f"(f3), "f"(f2));
                mhi[mt][2 * nt]     = h0;
                mhi[mt][2 * nt + 1] = h1;
                mlo[mt][2 * nt]     = l0;
                mlo[mt][2 * nt + 1] = l1;
            }
        }

        // ---- GEMM 2: p_pre = m @ wx1 + bx1 (A from registers) ----
        {
            int n0 = 2 * tig;
#pragma unroll
            for (int nt = 0; nt < 8; nt++) {
                float2 b = *(const float2*)&sbx1[8 * nt + n0];
                acc[0][nt][0] = b.x; acc[0][nt][1] = b.y;
                acc[0][nt][2] = b.x; acc[0][nt][3] = b.y;
                acc[1][nt][0] = b.x; acc[1][nt][1] = b.y;
                acc[1][nt][2] = b.x; acc[1][nt][3] = b.y;
            }
        }
        gemm_regA(smb, S_WXH, lane, mhi, mlo, acc);

        // ---- epilogue 2: q = silu(p); phi = q @ wx2 (quad-partial) ----
        {
            float ph[4][2] = {{0, 0}, {0, 0}, {0, 0}, {0, 0}};
#pragma unroll
            for (int mt = 0; mt < 2; mt++) {
#pragma unroll
                for (int nt = 0; nt < 8; nt++) {
                    int n0 = 8 * nt + 2 * tig;
                    float4 w = *(const float4*)&swx2[n0];
                    float q0 = silu(acc[mt][nt][0]);
                    float q1 = silu(acc[mt][nt][1]);
                    float q2 = silu(acc[mt][nt][2]);
                    float q3 = silu(acc[mt][nt][3]);
                    ph[2 * mt][0]     += q0 * w.x + q1 * w.z;
                    ph[2 * mt][1]     += q0 * w.y + q1 * w.w;
                    ph[2 * mt + 1][0] += q2 * w.x + q3 * w.z;
                    ph[2 * mt + 1][1] += q2 * w.y + q3 * w.w;
                }
            }
#pragma unroll
            for (int k = 0; k < 4; k++) {
#pragma unroll
                for (int c = 0; c < 2; c++) {
                    ph[k][c] += __shfl_xor_sync(0xffffffffu, ph[k][c], 1);
                    ph[k][c] += __shfl_xor_sync(0xffffffffu, ph[k][c], 2);
                }
            }
            if (tig == 0) {
#pragma unroll
                for (int k = 0; k < 4; k++) {
                    int row = 32 * warp + 16 * (k >> 1) + 8 * (k & 1) + gid;
                    sphi[row * 2] = ph[k][0];
                    sphi[row * 2 + 1] = ph[k][1];
                }
            }
        }
        __syncwarp();
        {
            float2 p = *(const float2*)&sphi[tid * 2];
            xacc[0] += p.x * sd0; xacc[1] += p.x * sd1; xacc[2] += p.x * sd2;
            xacc[3] += p.y * sd3; xacc[4] += p.y * sd4; xacc[5] += p.y * sd5;
        }
        __syncwarp();
    }

    // ---- reductions ----
#pragma unroll
    for (int i = 0; i < 16; i++) {
        aggv[i] += __shfl_xor_sync(0xffffffffu, aggv[i], 4);
        aggv[i] += __shfl_xor_sync(0xffffffffu, aggv[i], 8);
        aggv[i] += __shfl_xor_sync(0xffffffffu, aggv[i], 16);
    }
    if (lane < 4) {
#pragma unroll
        for (int nt = 0; nt < 8; nt++) {
            wpart[warp * 64 + 8 * nt + 2 * lane]     = aggv[2 * nt];
            wpart[warp * 64 + 8 * nt + 2 * lane + 1] = aggv[2 * nt + 1];
        }
    }
#pragma unroll
    for (int c = 0; c < 6; c++) {
        float v = xacc[c];
#pragma unroll
        for (int off = 16; off > 0; off >>= 1)
            v += __shfl_xor_sync(0xffffffffu, v, off);
        if (lane == 0) atomicAdd(&sxu[c], v);
    }
    __syncthreads();
    if (tid < 64)
        g_agg[r * HD + tid] = wpart[tid] + wpart[64 + tid] +
                              wpart[128 + tid] + wpart[192 + tid];
    if (tid < 6) g_xupd[r * 6 + tid] = sxu[tid];
}

// ---------------- node update (+ fused A/B precompute) ----------------
__global__ void k_update(const float* __restrict__ wh1,
                         const float* __restrict__ bh1,
                         const float* __restrict__ wh2,
                         const float* __restrict__ bh2,
                         const float* __restrict__ we1,
                         const float* __restrict__ be1,
                         int layer, int next_layer) {
    __shared__ float hs[4][HD], as[4][HD], us[4][HD];
    int g = threadIdx.x >> 6, j = threadIdx.x & 63;
    int t = blockIdx.x * 4 + g;
    const float* w1 = wh1 + layer * 128 * HD;
    const float* w2 = wh2 + layer * HD * HD;
    hs[g][j] = g_h[t * HD + j];
    as[g][j] = g_agg[t * HD + j];
    __syncthreads();
    float u = bh1[layer * HD + j];
#pragma unroll 8
    for (int i = 0; i < HD; i++) u += hs[g][i] * w1[i * HD + j];
#pragma unroll 8
    for (int i = 0; i < HD; i++) u += as[g][i] * w1[(64 + i) * HD + j];
    us[g][j] = silu(u);
    __syncthreads();
    float o = bh2[layer * HD + j];
#pragma unroll 8
    for (int i = 0; i < HD; i++) o += us[g][i] * w2[i * HD + j];
    float hn = hs[g][j] + o;
    g_h[t * HD + j] = hn;
    if (j < 6) g_x8[t * 8 + j] += g_xupd[t * 6 + j] * INV_T1;
    if (next_layer < LL) {
        hs[g][j] = hn;
        __syncthreads();
        const float* w = we1 + next_layer * 130 * HD;
        if (j < 32) {
            float alo = 0, ahi = 0;
            float blo = be1[next_layer * HD + j], bhi = be1[next_layer * HD + j + 32];
#pragma unroll 8
            for (int i = 0; i < HD; i++) {
                float hv = hs[g][i];
                alo += hv * w[i * HD + j];
                ahi += hv * w[i * HD + j + 32];
                blo += hv * w[(64 + i) * HD + j];
                bhi += hv * w[(64 + i) * HD + j + 32];
            }
            g_A2[t * 32 + j] = make_float2(alo, ahi);
            g_B2[t * 32 + j] = make_float2(blo, bhi);
        }
    }
}

// ---------------- final head ----------------
__global__ void k_final(const float* __restrict__ pos,
                        const float* __restrict__ w_head,
                        const float* __restrict__ b_head,
                        float* __restrict__ out) {
    __shared__ float hs[4][HD];
    int g = threadIdx.x >> 6, j = threadIdx.x & 63;
    int t = blockIdx.x * 4 + g;
    hs[g][j] = g_h[t * HD + j];
    __syncthreads();
    float o = b_head[j];
#pragma unroll 8
    for (int i = 0; i < HD; i++) o += hs[g][i] * w_head[i * OUTD + j];
    out[VEC_OUT + t * OUTD + j] = o;
    if (j < 6) out[t * 6 + j] = g_x8[t * 8 + j] - pos[t * 3 + (j % 3)];
}

// ---------------- launch ----------------
extern "C" void kernel_launch(void* const* d_in, const int* in_sizes, int n_in,
                              void* d_out, int out_size) {
    const float* positions = (const float*)d_in[0];
    const float* features  = (const float*)d_in[1];
    const float* w_emb     = (const float*)d_in[2];
    const float* b_emb     = (const float*)d_in[3];
    const float* we1       = (const float*)d_in[4];
    const float* be1       = (const float*)d_in[5];
    const float* we2       = (const float*)d_in[6];
    const float* be2       = (const float*)d_in[7];
    const float* wx1       = (const float*)d_in[8];
    const float* bx1       = (const float*)d_in[9];
    const float* wx2       = (const float*)d_in[10];
    const float* wh1       = (const float*)d_in[11];
    const float* bh1       = (const float*)d_in[12];
    const float* wh2       = (const float*)d_in[13];
    const float* bh2       = (const float*)d_in[14];
    const float* w_head    = (const float*)d_in[15];
    const float* b_head    = (const float*)d_in[16];
    float* out = (float*)d_out;

    cudaFuncSetAttribute(k_edge_mma, cudaFuncAttributeMaxDynamicSharedMemorySize,
                         EDGE_SMEM);

    k_init<<<NT / 4, 256>>>(features, w_emb, b_emb, positions, we1, be1);
    for (int l = 0; l < LL; l++) {
        k_edge_mma<<<NT, 128, EDGE_SMEM>>>(we1, we2, be2, wx1, bx1, wx2, l);
        k_update<<<NT / 4, 256>>>(wh1, bh1, wh2, bh2, we1, be1, l, l + 1);
    }
    k_final<<<NT / 4, 256>>>(positions, w_head, b_head, out);
}